// round 13
// baseline (speedup 1.0000x reference)
#include <cuda_runtime.h>
#include <cuda_bf16.h>
#include <cstdint>
#include <cstddef>

// ---------------------------------------------------------------------------
// QuantizedNN hybrid v9: v8 GEMM (128x128x64, 4 warps x 64x64, 3-stage,
// 2 CTA/SM, ~roofline) + vectorized/streaming aux pipeline.
// Integer-exact bf16 HMMA GEMM + round-3-exact chain amax / boundary repair.
// h bits identical to rounds 5/9/10/11.
// ---------------------------------------------------------------------------

#define BATCH   16384
#define IN_DIM  784
#define K1PAD   832          // 13 * 64 zero-padded K for layer 1
#define HIDDEN  4096
#define OUT_DIM 10

#define GBM 128
#define GBN 128
#define GBK 64
#define NSTAGE 3
#define STAGE_ELEMS ((GBM + GBN) * GBK)   // 16384 bf16 = 32KB per stage

#define LIST_CAP (1u << 22)
#define CAND_CAP (1u << 16)
#define TAU 3e-4f                          // bin-boundary margin (bin units)

// slots: 0=x,1=W1,2=W2,3=W3 | 4,5 = int amax h1,h2 | 6,7 = chain amax h1,h2
//        8,9 = repair counts L1,L2 | 10,11 = amax-candidate counts L1,L2
__device__ unsigned g_absmax_bits[16];
__device__ unsigned g_list[2 * LIST_CAP];
__device__ unsigned g_cand[2 * CAND_CAP];

__device__ __nv_bfloat16 g_xq [(size_t)BATCH  * K1PAD];
__device__ __nv_bfloat16 g_w1q[(size_t)HIDDEN * K1PAD];
__device__ __nv_bfloat16 g_w2q[(size_t)HIDDEN * HIDDEN];
__device__ __nv_bfloat16 g_w3q[(size_t)OUT_DIM * HIDDEN];
__device__ float         g_h1 [(size_t)BATCH * HIDDEN];
__device__ __nv_bfloat16 g_h1q[(size_t)BATCH * HIDDEN];
__device__ float         g_h2 [(size_t)BATCH * HIDDEN];
__device__ __nv_bfloat16 g_h2q[(size_t)BATCH * HIDDEN];

__device__ __forceinline__ float load_scale(int idx, float nlev) {
    float amax = __uint_as_float(g_absmax_bits[idx]);
    return fmaxf(__fdiv_rn(amax, nlev), 1e-8f);   // jnp.maximum(amax/n, 1e-8)
}

__global__ void init_stats_kernel() {
    if (threadIdx.x < 16) g_absmax_bits[threadIdx.x] = 0u;
}

__global__ void absmax_kernel(const float* __restrict__ x, int n4, int idx) {
    const float4* x4 = (const float4*)x;
    float m = 0.f;
    for (int i = blockIdx.x * blockDim.x + threadIdx.x; i < n4;
         i += gridDim.x * blockDim.x) {
        float4 v = x4[i];
        m = fmaxf(m, fmaxf(fmaxf(fabsf(v.x), fabsf(v.y)),
                           fmaxf(fabsf(v.z), fabsf(v.w))));
    }
#pragma unroll
    for (int o = 16; o; o >>= 1) m = fmaxf(m, __shfl_xor_sync(0xffffffffu, m, o));
    __shared__ float red[8];
    int lane = threadIdx.x & 31, w = threadIdx.x >> 5;
    if (lane == 0) red[w] = m;
    __syncthreads();
    if (threadIdx.x == 0) {
        float r = red[0];
        for (int i = 1; i < (int)(blockDim.x >> 5); i++) r = fmaxf(r, red[i]);
        atomicMax(&g_absmax_bits[idx], __float_as_uint(r));
    }
}

// integer quantize, 4 elems/thread: out = clip(round(v/s),-n,n) bf16 int.
// Kpad and K are multiples of 4 and pad boundary is 4-aligned.
__global__ void quantize_int_kernel(const float* __restrict__ in,
                                    __nv_bfloat16* __restrict__ out,
                                    int K, int Kpad, int statIdx, float nlev) {
    int c4 = blockIdx.x * blockDim.x + threadIdx.x;   // chunk of 4 cols
    int r  = blockIdx.y;
    int c  = c4 * 4;
    if (c >= Kpad) return;
    uint2 packed;
    if (c < K) {
        float s = load_scale(statIdx, nlev);
        float4 v = *(const float4*)(in + (size_t)r * K + c);
        float q0 = fminf(fmaxf(rintf(__fdiv_rn(v.x, s)), -nlev), nlev);
        float q1 = fminf(fmaxf(rintf(__fdiv_rn(v.y, s)), -nlev), nlev);
        float q2 = fminf(fmaxf(rintf(__fdiv_rn(v.z, s)), -nlev), nlev);
        float q3 = fminf(fmaxf(rintf(__fdiv_rn(v.w, s)), -nlev), nlev);
        __nv_bfloat162 lo = __floats2bfloat162_rn(q0, q1);
        __nv_bfloat162 hi = __floats2bfloat162_rn(q2, q3);
        packed.x = *(uint32_t*)&lo;
        packed.y = *(uint32_t*)&hi;
    } else {
        packed.x = 0u; packed.y = 0u;
    }
    *(uint2*)(out + (size_t)r * Kpad + c) = packed;
}

// Exact reference-matching value: ascending-k single-accumulator fmaf chain.
__device__ __forceinline__ float chain_value(const __nv_bfloat16* __restrict__ A,
                                             const __nv_bfloat16* __restrict__ W,
                                             const float* __restrict__ bias,
                                             int K, unsigned r, unsigned c,
                                             float sA, float sW) {
    const uint4* a4 = (const uint4*)(A + (size_t)r * K);
    const uint4* w4 = (const uint4*)(W + (size_t)c * K);
    float acc = 0.f;
    for (int kc = 0; kc < K / 8; kc++) {
        uint4 ua = __ldg(&a4[kc]);
        uint4 uw = __ldg(&w4[kc]);
        const __nv_bfloat162* pa = (const __nv_bfloat162*)&ua;
        const __nv_bfloat162* pw = (const __nv_bfloat162*)&uw;
#pragma unroll
        for (int j = 0; j < 4; j++) {
            float2 fa = __bfloat1622float2(pa[j]);
            float2 fw = __bfloat1622float2(pw[j]);
            acc = fmaf(__fmul_rn(fa.x, sA), __fmul_rn(fw.x, sW), acc);
            acc = fmaf(__fmul_rn(fa.y, sA), __fmul_rn(fw.y, sW), acc);
        }
    }
    return fmaxf(__fadd_rn(acc, __ldg(&bias[c])), 0.f);
}

// chain amax over epilogue-collected candidates (superset of global-thr set).
__global__ void chain_amax_cand_kernel(const float* __restrict__ h,
                                       const __nv_bfloat16* __restrict__ Aq,
                                       const __nv_bfloat16* __restrict__ Wq,
                                       const float* __restrict__ bias,
                                       int K, int intSlot, int chainSlot,
                                       int candSlot, unsigned candBase,
                                       int iA, float nA, int iW, float nW) {
    unsigned cnt = g_absmax_bits[candSlot];
    if (cnt > CAND_CAP) cnt = CAND_CAP;
    float amax = __uint_as_float(g_absmax_bits[intSlot]);
    float thr  = amax * (1.0f - 4e-6f);
    const float sA = load_scale(iA, nA);
    const float sW = load_scale(iW, nW);
    for (unsigned i = blockIdx.x * blockDim.x + threadIdx.x; i < cnt;
         i += gridDim.x * blockDim.x) {
        unsigned idx = g_cand[candBase + i];
        if (h[idx] >= thr) {
            unsigned r = idx >> 12, c = idx & 4095u;
            float hv = chain_value(Aq, Wq, bias, K, r, c, sA, sW);
            atomicMax(&g_absmax_bits[chainSlot], __float_as_uint(hv));
        }
    }
}

// quantize h with the CHAIN scale, 4 elems/thread; flag near-boundary.
__global__ void quantize_detect_kernel(const float* __restrict__ h,
                                       __nv_bfloat16* __restrict__ qout,
                                       int chainSlot, int cntSlot,
                                       unsigned listBase) {
    int i4 = blockIdx.x * blockDim.x + threadIdx.x;
    float s = load_scale(chainSlot, 7.f);
    float4 v = __ldcs((const float4*)h + i4);
    float q[4];
    unsigned flags = 0;
    const float* vp = (const float*)&v;
#pragma unroll
    for (int j = 0; j < 4; j++) {
        float t = __fdiv_rn(vp[j], s);
        float r = rintf(t);
        q[j] = fminf(fmaxf(r, -7.f), 7.f);
        if (fabsf(t - r) > 0.5f - TAU) flags |= (1u << j);
    }
    __nv_bfloat162 lo = __floats2bfloat162_rn(q[0], q[1]);
    __nv_bfloat162 hi = __floats2bfloat162_rn(q[2], q[3]);
    uint2 packed; packed.x = *(uint32_t*)&lo; packed.y = *(uint32_t*)&hi;
    *(uint2*)(qout + (size_t)i4 * 4) = packed;
    if (flags) {
#pragma unroll
        for (int j = 0; j < 4; j++) {
            if (flags & (1u << j)) {
                unsigned p = atomicAdd(&g_absmax_bits[cntSlot], 1u);
                if (p < LIST_CAP) g_list[listBase + p] = (unsigned)(i4 * 4 + j);
            }
        }
    }
}

// repair: recompute flagged elements with the exact chain, re-bin, overwrite.
__global__ void repair_kernel(const __nv_bfloat16* __restrict__ Aq,
                              const __nv_bfloat16* __restrict__ Wq,
                              const float* __restrict__ bias,
                              __nv_bfloat16* __restrict__ qout,
                              int K, int cntSlot, unsigned listBase,
                              int iA, float nA, int iW, float nW,
                              int chainSlot) {
    unsigned cnt = g_absmax_bits[cntSlot];
    if (cnt > LIST_CAP) cnt = LIST_CAP;
    const float sA = load_scale(iA, nA);
    const float sW = load_scale(iW, nW);
    const float sO = load_scale(chainSlot, 7.f);
    for (unsigned i = blockIdx.x * blockDim.x + threadIdx.x; i < cnt;
         i += gridDim.x * blockDim.x) {
        unsigned idx = g_list[listBase + i];
        unsigned r = idx >> 12, c = idx & 4095u;
        float hv = chain_value(Aq, Wq, bias, K, r, c, sA, sW);
        float t  = __fdiv_rn(hv, sO);
        float q  = fminf(fmaxf(rintf(t), -7.f), 7.f);
        qout[idx] = __float2bfloat16_rn(q);
    }
}

__device__ __forceinline__ uint32_t smem_u32(const void* p) {
    return (uint32_t)__cvta_generic_to_shared(p);
}

// One stage: A 128 rows x 128B + B 128 rows x 128B, xor-swizzled 16B chunks.
// 128 threads: lrow = tid>>3 (0..15), 8 row-groups each for A and B.
__device__ __forceinline__ void load_stage(__nv_bfloat16* stage,
                                           const __nv_bfloat16* __restrict__ A,
                                           const __nv_bfloat16* __restrict__ B,
                                           int K, int bm0, int bn0, int kt,
                                           int lrow, int lcol)
{
    __nv_bfloat16* as = stage;
    __nv_bfloat16* bs = stage + GBM * GBK;
    const int kbase = kt * GBK + (lcol << 3);
#pragma unroll
    for (int i = 0; i < 8; i++) {
        int r = i * 16 + lrow;
        uint32_t dst = smem_u32(as + r * GBK + ((lcol ^ (r & 7)) << 3));
        asm volatile("cp.async.cg.shared.global [%0], [%1], 16;\n"
                     :: "r"(dst), "l"(A + (size_t)(bm0 + r) * K + kbase));
    }
#pragma unroll
    for (int i = 0; i < 8; i++) {
        int r = i * 16 + lrow;
        uint32_t dst = smem_u32(bs + r * GBK + ((lcol ^ (r & 7)) << 3));
        asm volatile("cp.async.cg.shared.global [%0], [%1], 16;\n"
                     :: "r"(dst), "l"(B + (size_t)(bn0 + r) * K + kbase));
    }
    asm volatile("cp.async.commit_group;\n" ::: "memory");
}

// C = sc * (Aq @ Bq^T) + bias, relu, int amax -> iOutInt, amax candidates.
// 4 warps, each computing a 64x64 sub-tile. Streaming stores for C.
__global__ void __launch_bounds__(128, 2)
gemm_bf16_kernel(const __nv_bfloat16* __restrict__ A,
                 const __nv_bfloat16* __restrict__ B,
                 const float* __restrict__ bias,
                 float* __restrict__ C,
                 int M, int N, int K,
                 int iA, float nA, int iW, float nW,
                 int iOutInt, int candSlot, unsigned candBase)
{
    extern __shared__ __nv_bfloat16 smem[];
    const int tid  = threadIdx.x;
    const int lane = tid & 31;
    const int wid  = tid >> 5;
    const int wm   = wid >> 1;   // 0..1 : 64 rows
    const int wn   = wid & 1;    // 0..1 : 64 cols
    const int bm0  = blockIdx.y * GBM;
    const int bn0  = blockIdx.x * GBN;
    const int lrow = tid >> 3;   // 0..15
    const int lcol = tid & 7;    // 16B chunk

    float acc[4][8][4];
#pragma unroll
    for (int i = 0; i < 4; i++)
#pragma unroll
        for (int j = 0; j < 8; j++)
#pragma unroll
            for (int v = 0; v < 4; v++) acc[i][j][v] = 0.f;

    const int nkt = K / GBK;
    load_stage(smem, A, B, K, bm0, bn0, 0, lrow, lcol);
    if (nkt > 1) load_stage(smem + STAGE_ELEMS, A, B, K, bm0, bn0, 1, lrow, lcol);

    for (int kt = 0; kt < nkt; kt++) {
        if (kt + 1 < nkt) {
            asm volatile("cp.async.wait_group 1;\n" ::: "memory");
        } else {
            asm volatile("cp.async.wait_group 0;\n" ::: "memory");
        }
        __syncthreads();   // single barrier per iteration (3-stage buffer)

        if (kt + 2 < nkt) {
            load_stage(smem + ((kt + 2) % NSTAGE) * STAGE_ELEMS, A, B, K,
                       bm0, bn0, kt + 2, lrow, lcol);
        }

        const __nv_bfloat16* as = smem + (kt % NSTAGE) * STAGE_ELEMS;
        const __nv_bfloat16* bs = as + GBM * GBK;

#pragma unroll
        for (int s = 0; s < 4; s++) {
            uint32_t af[4][4];
#pragma unroll
            for (int im = 0; im < 4; im++) {
                int r  = wm * 64 + im * 16 + (lane & 15);
                int ch = (2 * s + (lane >> 4)) ^ (r & 7);
                uint32_t addr = smem_u32(as + r * GBK + ch * 8);
                asm volatile(
                    "ldmatrix.sync.aligned.m8n8.x4.shared.b16 {%0,%1,%2,%3}, [%4];"
                    : "=r"(af[im][0]), "=r"(af[im][1]), "=r"(af[im][2]), "=r"(af[im][3])
                    : "r"(addr));
            }
            uint32_t bfr[8][2];
#pragma unroll
            for (int p = 0; p < 4; p++) {
                int sub = lane >> 3;
                int jn  = 2 * p + (sub >> 1);
                int r   = wn * 64 + jn * 8 + (lane & 7);
                int ch  = (2 * s + (sub & 1)) ^ (r & 7);
                uint32_t addr = smem_u32(bs + r * GBK + ch * 8);
                asm volatile(
                    "ldmatrix.sync.aligned.m8n8.x4.shared.b16 {%0,%1,%2,%3}, [%4];"
                    : "=r"(bfr[2*p][0]), "=r"(bfr[2*p][1]),
                      "=r"(bfr[2*p+1][0]), "=r"(bfr[2*p+1][1])
                    : "r"(addr));
            }
#pragma unroll
            for (int im = 0; im < 4; im++)
#pragma unroll
                for (int jn = 0; jn < 8; jn++) {
                    asm volatile(
                        "mma.sync.aligned.m16n8k16.row.col.f32.bf16.bf16.f32 "
                        "{%0,%1,%2,%3}, {%4,%5,%6,%7}, {%8,%9}, {%0,%1,%2,%3};"
                        : "+f"(acc[im][jn][0]), "+f"(acc[im][jn][1]),
                          "+f"(acc[im][jn][2]), "+f"(acc[im][jn][3])
                        : "r"(af[im][0]), "r"(af[im][1]), "r"(af[im][2]), "r"(af[im][3]),
                          "r"(bfr[jn][0]), "r"(bfr[jn][1]));
                }
        }
    }

    const float sc = load_scale(iA, nA) * load_scale(iW, nW);
    const int g = lane >> 2, t = lane & 3;
    float lmax = 0.f;
#pragma unroll
    for (int im = 0; im < 4; im++) {
#pragma unroll
        for (int jn = 0; jn < 8; jn++) {
            int row = bm0 + wm * 64 + im * 16 + g;
            int col = bn0 + wn * 64 + jn * 8 + 2 * t;
            float bv0 = __ldg(&bias[col]), bv1 = __ldg(&bias[col + 1]);
            float v00 = fmaxf(fmaf(acc[im][jn][0], sc, bv0), 0.f);
            float v01 = fmaxf(fmaf(acc[im][jn][1], sc, bv1), 0.f);
            float v10 = fmaxf(fmaf(acc[im][jn][2], sc, bv0), 0.f);
            float v11 = fmaxf(fmaf(acc[im][jn][3], sc, bv1), 0.f);
            acc[im][jn][0] = v00; acc[im][jn][1] = v01;   // keep for candidates
            acc[im][jn][2] = v10; acc[im][jn][3] = v11;
            __stcs((float2*)&C[(size_t)row * N + col],       make_float2(v00, v01));
            __stcs((float2*)&C[(size_t)(row + 8) * N + col], make_float2(v10, v11));
            lmax = fmaxf(lmax, fmaxf(fmaxf(v00, v01), fmaxf(v10, v11)));
        }
    }
#pragma unroll
    for (int o = 16; o; o >>= 1)
        lmax = fmaxf(lmax, __shfl_xor_sync(0xffffffffu, lmax, o));
    __shared__ float smax[4];
    __shared__ float ctamax_sh;
    if (lane == 0) smax[wid] = lmax;
    __syncthreads();
    if (tid == 0) {
        float m = fmaxf(fmaxf(smax[0], smax[1]), fmaxf(smax[2], smax[3]));
        ctamax_sh = m;
        atomicMax(&g_absmax_bits[iOutInt], __float_as_uint(m));
    }
    __syncthreads();

    // append amax candidates: v >= cta_max*(1-4e-6) is a superset of the
    // global-threshold set (cta_max <= global_amax).
    const float cthr = ctamax_sh * (1.0f - 4e-6f);
#pragma unroll
    for (int im = 0; im < 4; im++) {
#pragma unroll
        for (int jn = 0; jn < 8; jn++) {
            int row = bm0 + wm * 64 + im * 16 + g;
            int col = bn0 + wn * 64 + jn * 8 + 2 * t;
#pragma unroll
            for (int v = 0; v < 4; v++) {
                if (acc[im][jn][v] >= cthr) {
                    unsigned idx = (unsigned)(row + (v >> 1) * 8) * 4096u
                                 + (unsigned)(col + (v & 1));
                    unsigned pos = atomicAdd(&g_absmax_bits[candSlot], 1u);
                    if (pos < CAND_CAP) g_cand[candBase + pos] = idx;
                }
            }
        }
    }
}

// Layer 3: exact integer warp-dot, out = sc*acc + b3 (order-free, no quant).
__global__ void __launch_bounds__(512)
layer3_kernel(const float* __restrict__ b3, float* __restrict__ out)
{
    extern __shared__ __nv_bfloat16 w3s[];   // [10][4096] bf16 = 80KB
    const int tid = threadIdx.x;
    {
        const uint4* src = (const uint4*)g_w3q;
        uint4* dst = (uint4*)w3s;
        for (int i = tid; i < OUT_DIM * HIDDEN / 8; i += 512) dst[i] = src[i];
    }
    __syncthreads();

    const int lane = tid & 31;
    const int w    = tid >> 5;
    const int m    = blockIdx.x * 16 + w;

    float acc[OUT_DIM];
#pragma unroll
    for (int n = 0; n < OUT_DIM; n++) acc[n] = 0.f;

    const uint32_t* arow = (const uint32_t*)(g_h2q + (size_t)m * HIDDEN);
    const uint32_t* ws   = (const uint32_t*)w3s;
    for (int k2 = lane; k2 < HIDDEN / 2; k2 += 32) {
        uint32_t av = arow[k2];
        float a0 = __uint_as_float(av << 16);
        float a1 = __uint_as_float(av & 0xffff0000u);
#pragma unroll
        for (int n = 0; n < OUT_DIM; n++) {
            uint32_t wv = ws[n * (HIDDEN / 2) + k2];
            acc[n] = fmaf(a0, __uint_as_float(wv << 16), acc[n]);
            acc[n] = fmaf(a1, __uint_as_float(wv & 0xffff0000u), acc[n]);
        }
    }
#pragma unroll
    for (int n = 0; n < OUT_DIM; n++)
#pragma unroll
        for (int o = 16; o; o >>= 1)
            acc[n] += __shfl_xor_sync(0xffffffffu, acc[n], o);

    if (lane == 0) {
        float sc = load_scale(7, 7.f) * load_scale(3, 127.f);
#pragma unroll
        for (int n = 0; n < OUT_DIM; n++)
            out[(size_t)m * OUT_DIM + n] = fmaf(acc[n], sc, b3[n]);
    }
}

extern "C" void kernel_launch(void* const* d_in, const int* in_sizes, int n_in,
                              void* d_out, int out_size) {
    const float* x  = (const float*)d_in[0];
    const float* W1 = (const float*)d_in[1];
    const float* b1 = (const float*)d_in[2];
    const float* W2 = (const float*)d_in[3];
    const float* b2 = (const float*)d_in[4];
    const float* W3 = (const float*)d_in[5];
    const float* b3 = (const float*)d_in[6];
    float* out = (float*)d_out;

    void* p;
    cudaGetSymbolAddress(&p, g_xq);  __nv_bfloat16* xq  = (__nv_bfloat16*)p;
    cudaGetSymbolAddress(&p, g_w1q); __nv_bfloat16* w1q = (__nv_bfloat16*)p;
    cudaGetSymbolAddress(&p, g_w2q); __nv_bfloat16* w2q = (__nv_bfloat16*)p;
    cudaGetSymbolAddress(&p, g_w3q); __nv_bfloat16* w3q = (__nv_bfloat16*)p;
    cudaGetSymbolAddress(&p, g_h1);  float*         h1  = (float*)p;
    cudaGetSymbolAddress(&p, g_h1q); __nv_bfloat16* h1q = (__nv_bfloat16*)p;
    cudaGetSymbolAddress(&p, g_h2);  float*         h2  = (float*)p;
    cudaGetSymbolAddress(&p, g_h2q); __nv_bfloat16* h2q = (__nv_bfloat16*)p;

    const size_t gemm_shm = (size_t)NSTAGE * STAGE_ELEMS * sizeof(__nv_bfloat16); // 96KB
    const size_t l3_shm   = (size_t)OUT_DIM * HIDDEN * sizeof(__nv_bfloat16);     // 80KB
    cudaFuncSetAttribute(gemm_bf16_kernel,
                         cudaFuncAttributeMaxDynamicSharedMemorySize, (int)gemm_shm);
    cudaFuncSetAttribute(layer3_kernel,
                         cudaFuncAttributeMaxDynamicSharedMemorySize, (int)l3_shm);

    init_stats_kernel<<<1, 32>>>();

    absmax_kernel<<<2048, 256>>>(x,  BATCH * IN_DIM / 4, 0);
    absmax_kernel<<<512,  256>>>(W1, HIDDEN * IN_DIM / 4, 1);
    absmax_kernel<<<2048, 256>>>(W2, HIDDEN * HIDDEN / 4, 2);
    absmax_kernel<<<40,   256>>>(W3, OUT_DIM * HIDDEN / 4, 3);

    { dim3 g((K1PAD / 4 + 255) / 256, BATCH);
      quantize_int_kernel<<<g, 256>>>(x,  xq,  IN_DIM, K1PAD, 0, 7.f); }
    { dim3 g((K1PAD / 4 + 255) / 256, HIDDEN);
      quantize_int_kernel<<<g, 256>>>(W1, w1q, IN_DIM, K1PAD, 1, 127.f); }
    { dim3 g(HIDDEN / 4 / 256, HIDDEN);
      quantize_int_kernel<<<g, 256>>>(W2, w2q, HIDDEN, HIDDEN, 2, 127.f); }
    { dim3 g(HIDDEN / 4 / 256, OUT_DIM);
      quantize_int_kernel<<<g, 256>>>(W3, w3q, HIDDEN, HIDDEN, 3, 127.f); }

    dim3 gg(HIDDEN / GBN, BATCH / GBM);  // (32, 128)
    const int NEL = BATCH * HIDDEN;      // 2^26

    // ---- Layer 1 ----
    gemm_bf16_kernel<<<gg, 128, gemm_shm>>>(xq, w1q, b1, h1,
                                            BATCH, HIDDEN, K1PAD,
                                            0, 7.f, 1, 127.f, 4, 10, 0u);
    chain_amax_cand_kernel<<<64, 256>>>(h1, xq, w1q, b1, K1PAD, 4, 6, 10, 0u,
                                        0, 7.f, 1, 127.f);
    quantize_detect_kernel<<<NEL / 1024, 256>>>(h1, h1q, 6, 8, 0u);
    repair_kernel<<<2048, 256>>>(xq, w1q, b1, h1q, K1PAD, 8, 0u,
                                 0, 7.f, 1, 127.f, 6);

    // ---- Layer 2 ----
    gemm_bf16_kernel<<<gg, 128, gemm_shm>>>(h1q, w2q, b2, h2,
                                            BATCH, HIDDEN, HIDDEN,
                                            6, 7.f, 2, 127.f, 5, 11, CAND_CAP);
    chain_amax_cand_kernel<<<64, 256>>>(h2, h1q, w2q, b2, HIDDEN, 5, 7, 11, CAND_CAP,
                                        6, 7.f, 2, 127.f);
    quantize_detect_kernel<<<NEL / 1024, 256>>>(h2, h2q, 7, 9, LIST_CAP);
    repair_kernel<<<2048, 256>>>(h1q, w2q, b2, h2q, HIDDEN, 9, LIST_CAP,
                                 6, 7.f, 2, 127.f, 7);

    // ---- Layer 3 ----
    layer3_kernel<<<BATCH / 16, 512, l3_shm>>>(b3, out);
}

// round 14
// speedup vs baseline: 1.0036x; 1.0036x over previous
#include <cuda_runtime.h>
#include <cuda_bf16.h>
#include <cstdint>
#include <cstddef>

// ---------------------------------------------------------------------------
// QuantizedNN hybrid v9: v8 GEMM (128x128x64, 4 warps x 64x64, 3-stage,
// 2 CTA/SM, ~roofline) + vectorized/streaming aux pipeline.
// Integer-exact bf16 HMMA GEMM + round-3-exact chain amax / boundary repair.
// h bits identical to rounds 5/9/10/11.
// ---------------------------------------------------------------------------

#define BATCH   16384
#define IN_DIM  784
#define K1PAD   832          // 13 * 64 zero-padded K for layer 1
#define HIDDEN  4096
#define OUT_DIM 10

#define GBM 128
#define GBN 128
#define GBK 64
#define NSTAGE 3
#define STAGE_ELEMS ((GBM + GBN) * GBK)   // 16384 bf16 = 32KB per stage

#define LIST_CAP (1u << 22)
#define CAND_CAP (1u << 16)
#define TAU 3e-4f                          // bin-boundary margin (bin units)

// slots: 0=x,1=W1,2=W2,3=W3 | 4,5 = int amax h1,h2 | 6,7 = chain amax h1,h2
//        8,9 = repair counts L1,L2 | 10,11 = amax-candidate counts L1,L2
__device__ unsigned g_absmax_bits[16];
__device__ unsigned g_list[2 * LIST_CAP];
__device__ unsigned g_cand[2 * CAND_CAP];

__device__ __nv_bfloat16 g_xq [(size_t)BATCH  * K1PAD];
__device__ __nv_bfloat16 g_w1q[(size_t)HIDDEN * K1PAD];
__device__ __nv_bfloat16 g_w2q[(size_t)HIDDEN * HIDDEN];
__device__ __nv_bfloat16 g_w3q[(size_t)OUT_DIM * HIDDEN];
__device__ float         g_h1 [(size_t)BATCH * HIDDEN];
__device__ __nv_bfloat16 g_h1q[(size_t)BATCH * HIDDEN];
__device__ float         g_h2 [(size_t)BATCH * HIDDEN];
__device__ __nv_bfloat16 g_h2q[(size_t)BATCH * HIDDEN];

__device__ __forceinline__ float load_scale(int idx, float nlev) {
    float amax = __uint_as_float(g_absmax_bits[idx]);
    return fmaxf(__fdiv_rn(amax, nlev), 1e-8f);   // jnp.maximum(amax/n, 1e-8)
}

__global__ void init_stats_kernel() {
    if (threadIdx.x < 16) g_absmax_bits[threadIdx.x] = 0u;
}

__global__ void absmax_kernel(const float* __restrict__ x, int n4, int idx) {
    const float4* x4 = (const float4*)x;
    float m = 0.f;
    for (int i = blockIdx.x * blockDim.x + threadIdx.x; i < n4;
         i += gridDim.x * blockDim.x) {
        float4 v = x4[i];
        m = fmaxf(m, fmaxf(fmaxf(fabsf(v.x), fabsf(v.y)),
                           fmaxf(fabsf(v.z), fabsf(v.w))));
    }
#pragma unroll
    for (int o = 16; o; o >>= 1) m = fmaxf(m, __shfl_xor_sync(0xffffffffu, m, o));
    __shared__ float red[8];
    int lane = threadIdx.x & 31, w = threadIdx.x >> 5;
    if (lane == 0) red[w] = m;
    __syncthreads();
    if (threadIdx.x == 0) {
        float r = red[0];
        for (int i = 1; i < (int)(blockDim.x >> 5); i++) r = fmaxf(r, red[i]);
        atomicMax(&g_absmax_bits[idx], __float_as_uint(r));
    }
}

// integer quantize, 4 elems/thread: out = clip(round(v/s),-n,n) bf16 int.
// Kpad and K are multiples of 4 and pad boundary is 4-aligned.
__global__ void quantize_int_kernel(const float* __restrict__ in,
                                    __nv_bfloat16* __restrict__ out,
                                    int K, int Kpad, int statIdx, float nlev) {
    int c4 = blockIdx.x * blockDim.x + threadIdx.x;   // chunk of 4 cols
    int r  = blockIdx.y;
    int c  = c4 * 4;
    if (c >= Kpad) return;
    uint2 packed;
    if (c < K) {
        float s = load_scale(statIdx, nlev);
        float4 v = *(const float4*)(in + (size_t)r * K + c);
        float q0 = fminf(fmaxf(rintf(__fdiv_rn(v.x, s)), -nlev), nlev);
        float q1 = fminf(fmaxf(rintf(__fdiv_rn(v.y, s)), -nlev), nlev);
        float q2 = fminf(fmaxf(rintf(__fdiv_rn(v.z, s)), -nlev), nlev);
        float q3 = fminf(fmaxf(rintf(__fdiv_rn(v.w, s)), -nlev), nlev);
        __nv_bfloat162 lo = __floats2bfloat162_rn(q0, q1);
        __nv_bfloat162 hi = __floats2bfloat162_rn(q2, q3);
        packed.x = *(uint32_t*)&lo;
        packed.y = *(uint32_t*)&hi;
    } else {
        packed.x = 0u; packed.y = 0u;
    }
    *(uint2*)(out + (size_t)r * Kpad + c) = packed;
}

// Exact reference-matching value: ascending-k single-accumulator fmaf chain.
__device__ __forceinline__ float chain_value(const __nv_bfloat16* __restrict__ A,
                                             const __nv_bfloat16* __restrict__ W,
                                             const float* __restrict__ bias,
                                             int K, unsigned r, unsigned c,
                                             float sA, float sW) {
    const uint4* a4 = (const uint4*)(A + (size_t)r * K);
    const uint4* w4 = (const uint4*)(W + (size_t)c * K);
    float acc = 0.f;
    for (int kc = 0; kc < K / 8; kc++) {
        uint4 ua = __ldg(&a4[kc]);
        uint4 uw = __ldg(&w4[kc]);
        const __nv_bfloat162* pa = (const __nv_bfloat162*)&ua;
        const __nv_bfloat162* pw = (const __nv_bfloat162*)&uw;
#pragma unroll
        for (int j = 0; j < 4; j++) {
            float2 fa = __bfloat1622float2(pa[j]);
            float2 fw = __bfloat1622float2(pw[j]);
            acc = fmaf(__fmul_rn(fa.x, sA), __fmul_rn(fw.x, sW), acc);
            acc = fmaf(__fmul_rn(fa.y, sA), __fmul_rn(fw.y, sW), acc);
        }
    }
    return fmaxf(__fadd_rn(acc, __ldg(&bias[c])), 0.f);
}

// chain amax over epilogue-collected candidates (superset of global-thr set).
__global__ void chain_amax_cand_kernel(const float* __restrict__ h,
                                       const __nv_bfloat16* __restrict__ Aq,
                                       const __nv_bfloat16* __restrict__ Wq,
                                       const float* __restrict__ bias,
                                       int K, int intSlot, int chainSlot,
                                       int candSlot, unsigned candBase,
                                       int iA, float nA, int iW, float nW) {
    unsigned cnt = g_absmax_bits[candSlot];
    if (cnt > CAND_CAP) cnt = CAND_CAP;
    float amax = __uint_as_float(g_absmax_bits[intSlot]);
    float thr  = amax * (1.0f - 4e-6f);
    const float sA = load_scale(iA, nA);
    const float sW = load_scale(iW, nW);
    for (unsigned i = blockIdx.x * blockDim.x + threadIdx.x; i < cnt;
         i += gridDim.x * blockDim.x) {
        unsigned idx = g_cand[candBase + i];
        if (h[idx] >= thr) {
            unsigned r = idx >> 12, c = idx & 4095u;
            float hv = chain_value(Aq, Wq, bias, K, r, c, sA, sW);
            atomicMax(&g_absmax_bits[chainSlot], __float_as_uint(hv));
        }
    }
}

// quantize h with the CHAIN scale, 4 elems/thread; flag near-boundary.
__global__ void quantize_detect_kernel(const float* __restrict__ h,
                                       __nv_bfloat16* __restrict__ qout,
                                       int chainSlot, int cntSlot,
                                       unsigned listBase) {
    int i4 = blockIdx.x * blockDim.x + threadIdx.x;
    float s = load_scale(chainSlot, 7.f);
    float4 v = __ldcs((const float4*)h + i4);
    float q[4];
    unsigned flags = 0;
    const float* vp = (const float*)&v;
#pragma unroll
    for (int j = 0; j < 4; j++) {
        float t = __fdiv_rn(vp[j], s);
        float r = rintf(t);
        q[j] = fminf(fmaxf(r, -7.f), 7.f);
        if (fabsf(t - r) > 0.5f - TAU) flags |= (1u << j);
    }
    __nv_bfloat162 lo = __floats2bfloat162_rn(q[0], q[1]);
    __nv_bfloat162 hi = __floats2bfloat162_rn(q[2], q[3]);
    uint2 packed; packed.x = *(uint32_t*)&lo; packed.y = *(uint32_t*)&hi;
    *(uint2*)(qout + (size_t)i4 * 4) = packed;
    if (flags) {
#pragma unroll
        for (int j = 0; j < 4; j++) {
            if (flags & (1u << j)) {
                unsigned p = atomicAdd(&g_absmax_bits[cntSlot], 1u);
                if (p < LIST_CAP) g_list[listBase + p] = (unsigned)(i4 * 4 + j);
            }
        }
    }
}

// repair: recompute flagged elements with the exact chain, re-bin, overwrite.
__global__ void repair_kernel(const __nv_bfloat16* __restrict__ Aq,
                              const __nv_bfloat16* __restrict__ Wq,
                              const float* __restrict__ bias,
                              __nv_bfloat16* __restrict__ qout,
                              int K, int cntSlot, unsigned listBase,
                              int iA, float nA, int iW, float nW,
                              int chainSlot) {
    unsigned cnt = g_absmax_bits[cntSlot];
    if (cnt > LIST_CAP) cnt = LIST_CAP;
    const float sA = load_scale(iA, nA);
    const float sW = load_scale(iW, nW);
    const float sO = load_scale(chainSlot, 7.f);
    for (unsigned i = blockIdx.x * blockDim.x + threadIdx.x; i < cnt;
         i += gridDim.x * blockDim.x) {
        unsigned idx = g_list[listBase + i];
        unsigned r = idx >> 12, c = idx & 4095u;
        float hv = chain_value(Aq, Wq, bias, K, r, c, sA, sW);
        float t  = __fdiv_rn(hv, sO);
        float q  = fminf(fmaxf(rintf(t), -7.f), 7.f);
        qout[idx] = __float2bfloat16_rn(q);
    }
}

__device__ __forceinline__ uint32_t smem_u32(const void* p) {
    return (uint32_t)__cvta_generic_to_shared(p);
}

// One stage: A 128 rows x 128B + B 128 rows x 128B, xor-swizzled 16B chunks.
// 128 threads: lrow = tid>>3 (0..15), 8 row-groups each for A and B.
__device__ __forceinline__ void load_stage(__nv_bfloat16* stage,
                                           const __nv_bfloat16* __restrict__ A,
                                           const __nv_bfloat16* __restrict__ B,
                                           int K, int bm0, int bn0, int kt,
                                           int lrow, int lcol)
{
    __nv_bfloat16* as = stage;
    __nv_bfloat16* bs = stage + GBM * GBK;
    const int kbase = kt * GBK + (lcol << 3);
#pragma unroll
    for (int i = 0; i < 8; i++) {
        int r = i * 16 + lrow;
        uint32_t dst = smem_u32(as + r * GBK + ((lcol ^ (r & 7)) << 3));
        asm volatile("cp.async.cg.shared.global [%0], [%1], 16;\n"
                     :: "r"(dst), "l"(A + (size_t)(bm0 + r) * K + kbase));
    }
#pragma unroll
    for (int i = 0; i < 8; i++) {
        int r = i * 16 + lrow;
        uint32_t dst = smem_u32(bs + r * GBK + ((lcol ^ (r & 7)) << 3));
        asm volatile("cp.async.cg.shared.global [%0], [%1], 16;\n"
                     :: "r"(dst), "l"(B + (size_t)(bn0 + r) * K + kbase));
    }
    asm volatile("cp.async.commit_group;\n" ::: "memory");
}

// C = sc * (Aq @ Bq^T) + bias, relu, int amax -> iOutInt, amax candidates.
// 4 warps, each computing a 64x64 sub-tile. Streaming stores for C.
__global__ void __launch_bounds__(128, 2)
gemm_bf16_kernel(const __nv_bfloat16* __restrict__ A,
                 const __nv_bfloat16* __restrict__ B,
                 const float* __restrict__ bias,
                 float* __restrict__ C,
                 int M, int N, int K,
                 int iA, float nA, int iW, float nW,
                 int iOutInt, int candSlot, unsigned candBase)
{
    extern __shared__ __nv_bfloat16 smem[];
    const int tid  = threadIdx.x;
    const int lane = tid & 31;
    const int wid  = tid >> 5;
    const int wm   = wid >> 1;   // 0..1 : 64 rows
    const int wn   = wid & 1;    // 0..1 : 64 cols
    const int bm0  = blockIdx.y * GBM;
    const int bn0  = blockIdx.x * GBN;
    const int lrow = tid >> 3;   // 0..15
    const int lcol = tid & 7;    // 16B chunk

    float acc[4][8][4];
#pragma unroll
    for (int i = 0; i < 4; i++)
#pragma unroll
        for (int j = 0; j < 8; j++)
#pragma unroll
            for (int v = 0; v < 4; v++) acc[i][j][v] = 0.f;

    const int nkt = K / GBK;
    load_stage(smem, A, B, K, bm0, bn0, 0, lrow, lcol);
    if (nkt > 1) load_stage(smem + STAGE_ELEMS, A, B, K, bm0, bn0, 1, lrow, lcol);

    for (int kt = 0; kt < nkt; kt++) {
        if (kt + 1 < nkt) {
            asm volatile("cp.async.wait_group 1;\n" ::: "memory");
        } else {
            asm volatile("cp.async.wait_group 0;\n" ::: "memory");
        }
        __syncthreads();   // single barrier per iteration (3-stage buffer)

        if (kt + 2 < nkt) {
            load_stage(smem + ((kt + 2) % NSTAGE) * STAGE_ELEMS, A, B, K,
                       bm0, bn0, kt + 2, lrow, lcol);
        }

        const __nv_bfloat16* as = smem + (kt % NSTAGE) * STAGE_ELEMS;
        const __nv_bfloat16* bs = as + GBM * GBK;

#pragma unroll
        for (int s = 0; s < 4; s++) {
            uint32_t af[4][4];
#pragma unroll
            for (int im = 0; im < 4; im++) {
                int r  = wm * 64 + im * 16 + (lane & 15);
                int ch = (2 * s + (lane >> 4)) ^ (r & 7);
                uint32_t addr = smem_u32(as + r * GBK + ch * 8);
                asm volatile(
                    "ldmatrix.sync.aligned.m8n8.x4.shared.b16 {%0,%1,%2,%3}, [%4];"
                    : "=r"(af[im][0]), "=r"(af[im][1]), "=r"(af[im][2]), "=r"(af[im][3])
                    : "r"(addr));
            }
            uint32_t bfr[8][2];
#pragma unroll
            for (int p = 0; p < 4; p++) {
                int sub = lane >> 3;
                int jn  = 2 * p + (sub >> 1);
                int r   = wn * 64 + jn * 8 + (lane & 7);
                int ch  = (2 * s + (sub & 1)) ^ (r & 7);
                uint32_t addr = smem_u32(bs + r * GBK + ch * 8);
                asm volatile(
                    "ldmatrix.sync.aligned.m8n8.x4.shared.b16 {%0,%1,%2,%3}, [%4];"
                    : "=r"(bfr[2*p][0]), "=r"(bfr[2*p][1]),
                      "=r"(bfr[2*p+1][0]), "=r"(bfr[2*p+1][1])
                    : "r"(addr));
            }
#pragma unroll
            for (int im = 0; im < 4; im++)
#pragma unroll
                for (int jn = 0; jn < 8; jn++) {
                    asm volatile(
                        "mma.sync.aligned.m16n8k16.row.col.f32.bf16.bf16.f32 "
                        "{%0,%1,%2,%3}, {%4,%5,%6,%7}, {%8,%9}, {%0,%1,%2,%3};"
                        : "+f"(acc[im][jn][0]), "+f"(acc[im][jn][1]),
                          "+f"(acc[im][jn][2]), "+f"(acc[im][jn][3])
                        : "r"(af[im][0]), "r"(af[im][1]), "r"(af[im][2]), "r"(af[im][3]),
                          "r"(bfr[jn][0]), "r"(bfr[jn][1]));
                }
        }
    }

    const float sc = load_scale(iA, nA) * load_scale(iW, nW);
    const int g = lane >> 2, t = lane & 3;
    float lmax = 0.f;
#pragma unroll
    for (int im = 0; im < 4; im++) {
#pragma unroll
        for (int jn = 0; jn < 8; jn++) {
            int row = bm0 + wm * 64 + im * 16 + g;
            int col = bn0 + wn * 64 + jn * 8 + 2 * t;
            float bv0 = __ldg(&bias[col]), bv1 = __ldg(&bias[col + 1]);
            float v00 = fmaxf(fmaf(acc[im][jn][0], sc, bv0), 0.f);
            float v01 = fmaxf(fmaf(acc[im][jn][1], sc, bv1), 0.f);
            float v10 = fmaxf(fmaf(acc[im][jn][2], sc, bv0), 0.f);
            float v11 = fmaxf(fmaf(acc[im][jn][3], sc, bv1), 0.f);
            acc[im][jn][0] = v00; acc[im][jn][1] = v01;   // keep for candidates
            acc[im][jn][2] = v10; acc[im][jn][3] = v11;
            __stcs((float2*)&C[(size_t)row * N + col],       make_float2(v00, v01));
            __stcs((float2*)&C[(size_t)(row + 8) * N + col], make_float2(v10, v11));
            lmax = fmaxf(lmax, fmaxf(fmaxf(v00, v01), fmaxf(v10, v11)));
        }
    }
#pragma unroll
    for (int o = 16; o; o >>= 1)
        lmax = fmaxf(lmax, __shfl_xor_sync(0xffffffffu, lmax, o));
    __shared__ float smax[4];
    __shared__ float ctamax_sh;
    if (lane == 0) smax[wid] = lmax;
    __syncthreads();
    if (tid == 0) {
        float m = fmaxf(fmaxf(smax[0], smax[1]), fmaxf(smax[2], smax[3]));
        ctamax_sh = m;
        atomicMax(&g_absmax_bits[iOutInt], __float_as_uint(m));
    }
    __syncthreads();

    // append amax candidates: v >= cta_max*(1-4e-6) is a superset of the
    // global-threshold set (cta_max <= global_amax).
    const float cthr = ctamax_sh * (1.0f - 4e-6f);
#pragma unroll
    for (int im = 0; im < 4; im++) {
#pragma unroll
        for (int jn = 0; jn < 8; jn++) {
            int row = bm0 + wm * 64 + im * 16 + g;
            int col = bn0 + wn * 64 + jn * 8 + 2 * t;
#pragma unroll
            for (int v = 0; v < 4; v++) {
                if (acc[im][jn][v] >= cthr) {
                    unsigned idx = (unsigned)(row + (v >> 1) * 8) * 4096u
                                 + (unsigned)(col + (v & 1));
                    unsigned pos = atomicAdd(&g_absmax_bits[candSlot], 1u);
                    if (pos < CAND_CAP) g_cand[candBase + pos] = idx;
                }
            }
        }
    }
}

// Layer 3: exact integer warp-dot, out = sc*acc + b3 (order-free, no quant).
__global__ void __launch_bounds__(512)
layer3_kernel(const float* __restrict__ b3, float* __restrict__ out)
{
    extern __shared__ __nv_bfloat16 w3s[];   // [10][4096] bf16 = 80KB
    const int tid = threadIdx.x;
    {
        const uint4* src = (const uint4*)g_w3q;
        uint4* dst = (uint4*)w3s;
        for (int i = tid; i < OUT_DIM * HIDDEN / 8; i += 512) dst[i] = src[i];
    }
    __syncthreads();

    const int lane = tid & 31;
    const int w    = tid >> 5;
    const int m    = blockIdx.x * 16 + w;

    float acc[OUT_DIM];
#pragma unroll
    for (int n = 0; n < OUT_DIM; n++) acc[n] = 0.f;

    const uint32_t* arow = (const uint32_t*)(g_h2q + (size_t)m * HIDDEN);
    const uint32_t* ws   = (const uint32_t*)w3s;
    for (int k2 = lane; k2 < HIDDEN / 2; k2 += 32) {
        uint32_t av = arow[k2];
        float a0 = __uint_as_float(av << 16);
        float a1 = __uint_as_float(av & 0xffff0000u);
#pragma unroll
        for (int n = 0; n < OUT_DIM; n++) {
            uint32_t wv = ws[n * (HIDDEN / 2) + k2];
            acc[n] = fmaf(a0, __uint_as_float(wv << 16), acc[n]);
            acc[n] = fmaf(a1, __uint_as_float(wv & 0xffff0000u), acc[n]);
        }
    }
#pragma unroll
    for (int n = 0; n < OUT_DIM; n++)
#pragma unroll
        for (int o = 16; o; o >>= 1)
            acc[n] += __shfl_xor_sync(0xffffffffu, acc[n], o);

    if (lane == 0) {
        float sc = load_scale(7, 7.f) * load_scale(3, 127.f);
#pragma unroll
        for (int n = 0; n < OUT_DIM; n++)
            out[(size_t)m * OUT_DIM + n] = fmaf(acc[n], sc, b3[n]);
    }
}

extern "C" void kernel_launch(void* const* d_in, const int* in_sizes, int n_in,
                              void* d_out, int out_size) {
    const float* x  = (const float*)d_in[0];
    const float* W1 = (const float*)d_in[1];
    const float* b1 = (const float*)d_in[2];
    const float* W2 = (const float*)d_in[3];
    const float* b2 = (const float*)d_in[4];
    const float* W3 = (const float*)d_in[5];
    const float* b3 = (const float*)d_in[6];
    float* out = (float*)d_out;

    void* p;
    cudaGetSymbolAddress(&p, g_xq);  __nv_bfloat16* xq  = (__nv_bfloat16*)p;
    cudaGetSymbolAddress(&p, g_w1q); __nv_bfloat16* w1q = (__nv_bfloat16*)p;
    cudaGetSymbolAddress(&p, g_w2q); __nv_bfloat16* w2q = (__nv_bfloat16*)p;
    cudaGetSymbolAddress(&p, g_w3q); __nv_bfloat16* w3q = (__nv_bfloat16*)p;
    cudaGetSymbolAddress(&p, g_h1);  float*         h1  = (float*)p;
    cudaGetSymbolAddress(&p, g_h1q); __nv_bfloat16* h1q = (__nv_bfloat16*)p;
    cudaGetSymbolAddress(&p, g_h2);  float*         h2  = (float*)p;
    cudaGetSymbolAddress(&p, g_h2q); __nv_bfloat16* h2q = (__nv_bfloat16*)p;

    const size_t gemm_shm = (size_t)NSTAGE * STAGE_ELEMS * sizeof(__nv_bfloat16); // 96KB
    const size_t l3_shm   = (size_t)OUT_DIM * HIDDEN * sizeof(__nv_bfloat16);     // 80KB
    cudaFuncSetAttribute(gemm_bf16_kernel,
                         cudaFuncAttributeMaxDynamicSharedMemorySize, (int)gemm_shm);
    cudaFuncSetAttribute(layer3_kernel,
                         cudaFuncAttributeMaxDynamicSharedMemorySize, (int)l3_shm);

    init_stats_kernel<<<1, 32>>>();

    absmax_kernel<<<2048, 256>>>(x,  BATCH * IN_DIM / 4, 0);
    absmax_kernel<<<512,  256>>>(W1, HIDDEN * IN_DIM / 4, 1);
    absmax_kernel<<<2048, 256>>>(W2, HIDDEN * HIDDEN / 4, 2);
    absmax_kernel<<<40,   256>>>(W3, OUT_DIM * HIDDEN / 4, 3);

    { dim3 g((K1PAD / 4 + 255) / 256, BATCH);
      quantize_int_kernel<<<g, 256>>>(x,  xq,  IN_DIM, K1PAD, 0, 7.f); }
    { dim3 g((K1PAD / 4 + 255) / 256, HIDDEN);
      quantize_int_kernel<<<g, 256>>>(W1, w1q, IN_DIM, K1PAD, 1, 127.f); }
    { dim3 g(HIDDEN / 4 / 256, HIDDEN);
      quantize_int_kernel<<<g, 256>>>(W2, w2q, HIDDEN, HIDDEN, 2, 127.f); }
    { dim3 g(HIDDEN / 4 / 256, OUT_DIM);
      quantize_int_kernel<<<g, 256>>>(W3, w3q, HIDDEN, HIDDEN, 3, 127.f); }

    dim3 gg(HIDDEN / GBN, BATCH / GBM);  // (32, 128)
    const int NEL = BATCH * HIDDEN;      // 2^26

    // ---- Layer 1 ----
    gemm_bf16_kernel<<<gg, 128, gemm_shm>>>(xq, w1q, b1, h1,
                                            BATCH, HIDDEN, K1PAD,
                                            0, 7.f, 1, 127.f, 4, 10, 0u);
    chain_amax_cand_kernel<<<64, 256>>>(h1, xq, w1q, b1, K1PAD, 4, 6, 10, 0u,
                                        0, 7.f, 1, 127.f);
    quantize_detect_kernel<<<NEL / 1024, 256>>>(h1, h1q, 6, 8, 0u);
    repair_kernel<<<2048, 256>>>(xq, w1q, b1, h1q, K1PAD, 8, 0u,
                                 0, 7.f, 1, 127.f, 6);

    // ---- Layer 2 ----
    gemm_bf16_kernel<<<gg, 128, gemm_shm>>>(h1q, w2q, b2, h2,
                                            BATCH, HIDDEN, HIDDEN,
                                            6, 7.f, 2, 127.f, 5, 11, CAND_CAP);
    chain_amax_cand_kernel<<<64, 256>>>(h2, h1q, w2q, b2, HIDDEN, 5, 7, 11, CAND_CAP,
                                        6, 7.f, 2, 127.f);
    quantize_detect_kernel<<<NEL / 1024, 256>>>(h2, h2q, 7, 9, LIST_CAP);
    repair_kernel<<<2048, 256>>>(h1q, w2q, b2, h2q, HIDDEN, 9, LIST_CAP,
                                 6, 7.f, 2, 127.f, 7);

    // ---- Layer 3 ----
    layer3_kernel<<<BATCH / 16, 512, l3_shm>>>(b3, out);
}

// round 15
// speedup vs baseline: 1.0091x; 1.0055x over previous
#include <cuda_runtime.h>
#include <cuda_bf16.h>
#include <cstdint>
#include <cstddef>

// ---------------------------------------------------------------------------
// QuantizedNN hybrid v10: v9 GEMM (128x128x64, 4 warps x 64x64, 3-stage,
// 2 CTA/SM, ~HMMA roofline) + fused absmax / fused quantize launches.
// Integer-exact bf16 HMMA GEMM + round-3-exact chain amax / boundary repair.
// h bits identical to rounds 5..14.
// ---------------------------------------------------------------------------

#define BATCH   16384
#define IN_DIM  784
#define K1PAD   832          // 13 * 64 zero-padded K for layer 1
#define HIDDEN  4096
#define OUT_DIM 10

#define GBM 128
#define GBN 128
#define GBK 64
#define NSTAGE 3
#define STAGE_ELEMS ((GBM + GBN) * GBK)   // 16384 bf16 = 32KB per stage

#define LIST_CAP (1u << 22)
#define CAND_CAP (1u << 16)
#define TAU 3e-4f                          // bin-boundary margin (bin units)

// slots: 0=x,1=W1,2=W2,3=W3 | 4,5 = int amax h1,h2 | 6,7 = chain amax h1,h2
//        8,9 = repair counts L1,L2 | 10,11 = amax-candidate counts L1,L2
__device__ unsigned g_absmax_bits[16];
__device__ unsigned g_list[2 * LIST_CAP];
__device__ unsigned g_cand[2 * CAND_CAP];

__device__ __nv_bfloat16 g_xq [(size_t)BATCH  * K1PAD];
__device__ __nv_bfloat16 g_w1q[(size_t)HIDDEN * K1PAD];
__device__ __nv_bfloat16 g_w2q[(size_t)HIDDEN * HIDDEN];
__device__ __nv_bfloat16 g_w3q[(size_t)OUT_DIM * HIDDEN];
__device__ float         g_h1 [(size_t)BATCH * HIDDEN];
__device__ __nv_bfloat16 g_h1q[(size_t)BATCH * HIDDEN];
__device__ float         g_h2 [(size_t)BATCH * HIDDEN];
__device__ __nv_bfloat16 g_h2q[(size_t)BATCH * HIDDEN];

__device__ __forceinline__ float load_scale(int idx, float nlev) {
    float amax = __uint_as_float(g_absmax_bits[idx]);
    return fmaxf(__fdiv_rn(amax, nlev), 1e-8f);   // jnp.maximum(amax/n, 1e-8)
}

__global__ void init_stats_kernel() {
    if (threadIdx.x < 16) g_absmax_bits[threadIdx.x] = 0u;
}

// Fused absmax over 4 tensors: blockIdx.y = tensor id (slot id).
struct AbsSeg { const float* p; int n4; };

__global__ void absmax4_kernel(AbsSeg s0, AbsSeg s1, AbsSeg s2, AbsSeg s3) {
    AbsSeg seg = (blockIdx.y == 0) ? s0 : (blockIdx.y == 1) ? s1
               : (blockIdx.y == 2) ? s2 : s3;
    const float4* x4 = (const float4*)seg.p;
    float m = 0.f;
    for (int i = blockIdx.x * blockDim.x + threadIdx.x; i < seg.n4;
         i += gridDim.x * blockDim.x) {
        float4 v = x4[i];
        m = fmaxf(m, fmaxf(fmaxf(fabsf(v.x), fabsf(v.y)),
                           fmaxf(fabsf(v.z), fabsf(v.w))));
    }
#pragma unroll
    for (int o = 16; o; o >>= 1) m = fmaxf(m, __shfl_xor_sync(0xffffffffu, m, o));
    __shared__ float red[8];
    int lane = threadIdx.x & 31, w = threadIdx.x >> 5;
    if (lane == 0) red[w] = m;
    __syncthreads();
    if (threadIdx.x == 0) {
        float r = red[0];
        for (int i = 1; i < (int)(blockDim.x >> 5); i++) r = fmaxf(r, red[i]);
        atomicMax(&g_absmax_bits[blockIdx.y], __float_as_uint(r));
    }
}

// Fused integer quantize over 4 tensors: blockIdx.y = segment.
// Per-element ops identical to prior rounds (bit-identical outputs).
struct QSeg {
    const float* in; __nv_bfloat16* out;
    int K, Kpad, statIdx, nchunk;   // nchunk = rows * Kpad/4
    float nlev;
};

__global__ void quantize4_kernel(QSeg s0, QSeg s1, QSeg s2, QSeg s3) {
    QSeg seg = (blockIdx.y == 0) ? s0 : (blockIdx.y == 1) ? s1
             : (blockIdx.y == 2) ? s2 : s3;
    const int kp4 = seg.Kpad >> 2;
    const float s = load_scale(seg.statIdx, seg.nlev);
    const float nlev = seg.nlev;
    for (int idx = blockIdx.x * blockDim.x + threadIdx.x; idx < seg.nchunk;
         idx += gridDim.x * blockDim.x) {
        int r  = idx / kp4;
        int c  = (idx - r * kp4) * 4;
        uint2 packed;
        if (c < seg.K) {
            float4 v = *(const float4*)(seg.in + (size_t)r * seg.K + c);
            float q0 = fminf(fmaxf(rintf(__fdiv_rn(v.x, s)), -nlev), nlev);
            float q1 = fminf(fmaxf(rintf(__fdiv_rn(v.y, s)), -nlev), nlev);
            float q2 = fminf(fmaxf(rintf(__fdiv_rn(v.z, s)), -nlev), nlev);
            float q3 = fminf(fmaxf(rintf(__fdiv_rn(v.w, s)), -nlev), nlev);
            __nv_bfloat162 lo = __floats2bfloat162_rn(q0, q1);
            __nv_bfloat162 hi = __floats2bfloat162_rn(q2, q3);
            packed.x = *(uint32_t*)&lo;
            packed.y = *(uint32_t*)&hi;
        } else {
            packed.x = 0u; packed.y = 0u;
        }
        *(uint2*)(seg.out + (size_t)r * seg.Kpad + c) = packed;
    }
}

// Exact reference-matching value: ascending-k single-accumulator fmaf chain.
__device__ __forceinline__ float chain_value(const __nv_bfloat16* __restrict__ A,
                                             const __nv_bfloat16* __restrict__ W,
                                             const float* __restrict__ bias,
                                             int K, unsigned r, unsigned c,
                                             float sA, float sW) {
    const uint4* a4 = (const uint4*)(A + (size_t)r * K);
    const uint4* w4 = (const uint4*)(W + (size_t)c * K);
    float acc = 0.f;
    for (int kc = 0; kc < K / 8; kc++) {
        uint4 ua = __ldg(&a4[kc]);
        uint4 uw = __ldg(&w4[kc]);
        const __nv_bfloat162* pa = (const __nv_bfloat162*)&ua;
        const __nv_bfloat162* pw = (const __nv_bfloat162*)&uw;
#pragma unroll
        for (int j = 0; j < 4; j++) {
            float2 fa = __bfloat1622float2(pa[j]);
            float2 fw = __bfloat1622float2(pw[j]);
            acc = fmaf(__fmul_rn(fa.x, sA), __fmul_rn(fw.x, sW), acc);
            acc = fmaf(__fmul_rn(fa.y, sA), __fmul_rn(fw.y, sW), acc);
        }
    }
    return fmaxf(__fadd_rn(acc, __ldg(&bias[c])), 0.f);
}

// chain amax over epilogue-collected candidates (superset of global-thr set).
__global__ void chain_amax_cand_kernel(const float* __restrict__ h,
                                       const __nv_bfloat16* __restrict__ Aq,
                                       const __nv_bfloat16* __restrict__ Wq,
                                       const float* __restrict__ bias,
                                       int K, int intSlot, int chainSlot,
                                       int candSlot, unsigned candBase,
                                       int iA, float nA, int iW, float nW) {
    unsigned cnt = g_absmax_bits[candSlot];
    if (cnt > CAND_CAP) cnt = CAND_CAP;
    float amax = __uint_as_float(g_absmax_bits[intSlot]);
    float thr  = amax * (1.0f - 4e-6f);
    const float sA = load_scale(iA, nA);
    const float sW = load_scale(iW, nW);
    for (unsigned i = blockIdx.x * blockDim.x + threadIdx.x; i < cnt;
         i += gridDim.x * blockDim.x) {
        unsigned idx = g_cand[candBase + i];
        if (h[idx] >= thr) {
            unsigned r = idx >> 12, c = idx & 4095u;
            float hv = chain_value(Aq, Wq, bias, K, r, c, sA, sW);
            atomicMax(&g_absmax_bits[chainSlot], __float_as_uint(hv));
        }
    }
}

// quantize h with the CHAIN scale, 4 elems/thread; flag near-boundary.
__global__ void quantize_detect_kernel(const float* __restrict__ h,
                                       __nv_bfloat16* __restrict__ qout,
                                       int chainSlot, int cntSlot,
                                       unsigned listBase) {
    int i4 = blockIdx.x * blockDim.x + threadIdx.x;
    float s = load_scale(chainSlot, 7.f);
    float4 v = __ldcs((const float4*)h + i4);
    float q[4];
    unsigned flags = 0;
    const float* vp = (const float*)&v;
#pragma unroll
    for (int j = 0; j < 4; j++) {
        float t = __fdiv_rn(vp[j], s);
        float r = rintf(t);
        q[j] = fminf(fmaxf(r, -7.f), 7.f);
        if (fabsf(t - r) > 0.5f - TAU) flags |= (1u << j);
    }
    __nv_bfloat162 lo = __floats2bfloat162_rn(q[0], q[1]);
    __nv_bfloat162 hi = __floats2bfloat162_rn(q[2], q[3]);
    uint2 packed; packed.x = *(uint32_t*)&lo; packed.y = *(uint32_t*)&hi;
    *(uint2*)(qout + (size_t)i4 * 4) = packed;
    if (flags) {
#pragma unroll
        for (int j = 0; j < 4; j++) {
            if (flags & (1u << j)) {
                unsigned p = atomicAdd(&g_absmax_bits[cntSlot], 1u);
                if (p < LIST_CAP) g_list[listBase + p] = (unsigned)(i4 * 4 + j);
            }
        }
    }
}

// repair: recompute flagged elements with the exact chain, re-bin, overwrite.
__global__ void repair_kernel(const __nv_bfloat16* __restrict__ Aq,
                              const __nv_bfloat16* __restrict__ Wq,
                              const float* __restrict__ bias,
                              __nv_bfloat16* __restrict__ qout,
                              int K, int cntSlot, unsigned listBase,
                              int iA, float nA, int iW, float nW,
                              int chainSlot) {
    unsigned cnt = g_absmax_bits[cntSlot];
    if (cnt > LIST_CAP) cnt = LIST_CAP;
    const float sA = load_scale(iA, nA);
    const float sW = load_scale(iW, nW);
    const float sO = load_scale(chainSlot, 7.f);
    for (unsigned i = blockIdx.x * blockDim.x + threadIdx.x; i < cnt;
         i += gridDim.x * blockDim.x) {
        unsigned idx = g_list[listBase + i];
        unsigned r = idx >> 12, c = idx & 4095u;
        float hv = chain_value(Aq, Wq, bias, K, r, c, sA, sW);
        float t  = __fdiv_rn(hv, sO);
        float q  = fminf(fmaxf(rintf(t), -7.f), 7.f);
        qout[idx] = __float2bfloat16_rn(q);
    }
}

__device__ __forceinline__ uint32_t smem_u32(const void* p) {
    return (uint32_t)__cvta_generic_to_shared(p);
}

// One stage: A 128 rows x 128B + B 128 rows x 128B, xor-swizzled 16B chunks.
// 128 threads: lrow = tid>>3 (0..15), 8 row-groups each for A and B.
__device__ __forceinline__ void load_stage(__nv_bfloat16* stage,
                                           const __nv_bfloat16* __restrict__ A,
                                           const __nv_bfloat16* __restrict__ B,
                                           int K, int bm0, int bn0, int kt,
                                           int lrow, int lcol)
{
    __nv_bfloat16* as = stage;
    __nv_bfloat16* bs = stage + GBM * GBK;
    const int kbase = kt * GBK + (lcol << 3);
#pragma unroll
    for (int i = 0; i < 8; i++) {
        int r = i * 16 + lrow;
        uint32_t dst = smem_u32(as + r * GBK + ((lcol ^ (r & 7)) << 3));
        asm volatile("cp.async.cg.shared.global [%0], [%1], 16;\n"
                     :: "r"(dst), "l"(A + (size_t)(bm0 + r) * K + kbase));
    }
#pragma unroll
    for (int i = 0; i < 8; i++) {
        int r = i * 16 + lrow;
        uint32_t dst = smem_u32(bs + r * GBK + ((lcol ^ (r & 7)) << 3));
        asm volatile("cp.async.cg.shared.global [%0], [%1], 16;\n"
                     :: "r"(dst), "l"(B + (size_t)(bn0 + r) * K + kbase));
    }
    asm volatile("cp.async.commit_group;\n" ::: "memory");
}

// C = sc * (Aq @ Bq^T) + bias, relu, int amax -> iOutInt, amax candidates.
// 4 warps, each computing a 64x64 sub-tile. Streaming stores for C.
__global__ void __launch_bounds__(128, 2)
gemm_bf16_kernel(const __nv_bfloat16* __restrict__ A,
                 const __nv_bfloat16* __restrict__ B,
                 const float* __restrict__ bias,
                 float* __restrict__ C,
                 int M, int N, int K,
                 int iA, float nA, int iW, float nW,
                 int iOutInt, int candSlot, unsigned candBase)
{
    extern __shared__ __nv_bfloat16 smem[];
    const int tid  = threadIdx.x;
    const int lane = tid & 31;
    const int wid  = tid >> 5;
    const int wm   = wid >> 1;   // 0..1 : 64 rows
    const int wn   = wid & 1;    // 0..1 : 64 cols
    const int bm0  = blockIdx.y * GBM;
    const int bn0  = blockIdx.x * GBN;
    const int lrow = tid >> 3;   // 0..15
    const int lcol = tid & 7;    // 16B chunk

    float acc[4][8][4];
#pragma unroll
    for (int i = 0; i < 4; i++)
#pragma unroll
        for (int j = 0; j < 8; j++)
#pragma unroll
            for (int v = 0; v < 4; v++) acc[i][j][v] = 0.f;

    const int nkt = K / GBK;
    load_stage(smem, A, B, K, bm0, bn0, 0, lrow, lcol);
    if (nkt > 1) load_stage(smem + STAGE_ELEMS, A, B, K, bm0, bn0, 1, lrow, lcol);

    for (int kt = 0; kt < nkt; kt++) {
        if (kt + 1 < nkt) {
            asm volatile("cp.async.wait_group 1;\n" ::: "memory");
        } else {
            asm volatile("cp.async.wait_group 0;\n" ::: "memory");
        }
        __syncthreads();   // single barrier per iteration (3-stage buffer)

        if (kt + 2 < nkt) {
            load_stage(smem + ((kt + 2) % NSTAGE) * STAGE_ELEMS, A, B, K,
                       bm0, bn0, kt + 2, lrow, lcol);
        }

        const __nv_bfloat16* as = smem + (kt % NSTAGE) * STAGE_ELEMS;
        const __nv_bfloat16* bs = as + GBM * GBK;

#pragma unroll
        for (int s = 0; s < 4; s++) {
            uint32_t af[4][4];
#pragma unroll
            for (int im = 0; im < 4; im++) {
                int r  = wm * 64 + im * 16 + (lane & 15);
                int ch = (2 * s + (lane >> 4)) ^ (r & 7);
                uint32_t addr = smem_u32(as + r * GBK + ch * 8);
                asm volatile(
                    "ldmatrix.sync.aligned.m8n8.x4.shared.b16 {%0,%1,%2,%3}, [%4];"
                    : "=r"(af[im][0]), "=r"(af[im][1]), "=r"(af[im][2]), "=r"(af[im][3])
                    : "r"(addr));
            }
            uint32_t bfr[8][2];
#pragma unroll
            for (int p = 0; p < 4; p++) {
                int sub = lane >> 3;
                int jn  = 2 * p + (sub >> 1);
                int r   = wn * 64 + jn * 8 + (lane & 7);
                int ch  = (2 * s + (sub & 1)) ^ (r & 7);
                uint32_t addr = smem_u32(bs + r * GBK + ch * 8);
                asm volatile(
                    "ldmatrix.sync.aligned.m8n8.x4.shared.b16 {%0,%1,%2,%3}, [%4];"
                    : "=r"(bfr[2*p][0]), "=r"(bfr[2*p][1]),
                      "=r"(bfr[2*p+1][0]), "=r"(bfr[2*p+1][1])
                    : "r"(addr));
            }
#pragma unroll
            for (int im = 0; im < 4; im++)
#pragma unroll
                for (int jn = 0; jn < 8; jn++) {
                    asm volatile(
                        "mma.sync.aligned.m16n8k16.row.col.f32.bf16.bf16.f32 "
                        "{%0,%1,%2,%3}, {%4,%5,%6,%7}, {%8,%9}, {%0,%1,%2,%3};"
                        : "+f"(acc[im][jn][0]), "+f"(acc[im][jn][1]),
                          "+f"(acc[im][jn][2]), "+f"(acc[im][jn][3])
                        : "r"(af[im][0]), "r"(af[im][1]), "r"(af[im][2]), "r"(af[im][3]),
                          "r"(bfr[jn][0]), "r"(bfr[jn][1]));
                }
        }
    }

    const float sc = load_scale(iA, nA) * load_scale(iW, nW);
    const int g = lane >> 2, t = lane & 3;
    float lmax = 0.f;
#pragma unroll
    for (int im = 0; im < 4; im++) {
#pragma unroll
        for (int jn = 0; jn < 8; jn++) {
            int row = bm0 + wm * 64 + im * 16 + g;
            int col = bn0 + wn * 64 + jn * 8 + 2 * t;
            float bv0 = __ldg(&bias[col]), bv1 = __ldg(&bias[col + 1]);
            float v00 = fmaxf(fmaf(acc[im][jn][0], sc, bv0), 0.f);
            float v01 = fmaxf(fmaf(acc[im][jn][1], sc, bv1), 0.f);
            float v10 = fmaxf(fmaf(acc[im][jn][2], sc, bv0), 0.f);
            float v11 = fmaxf(fmaf(acc[im][jn][3], sc, bv1), 0.f);
            acc[im][jn][0] = v00; acc[im][jn][1] = v01;   // keep for candidates
            acc[im][jn][2] = v10; acc[im][jn][3] = v11;
            __stcs((float2*)&C[(size_t)row * N + col],       make_float2(v00, v01));
            __stcs((float2*)&C[(size_t)(row + 8) * N + col], make_float2(v10, v11));
            lmax = fmaxf(lmax, fmaxf(fmaxf(v00, v01), fmaxf(v10, v11)));
        }
    }
#pragma unroll
    for (int o = 16; o; o >>= 1)
        lmax = fmaxf(lmax, __shfl_xor_sync(0xffffffffu, lmax, o));
    __shared__ float smax[4];
    __shared__ float ctamax_sh;
    if (lane == 0) smax[wid] = lmax;
    __syncthreads();
    if (tid == 0) {
        float m = fmaxf(fmaxf(smax[0], smax[1]), fmaxf(smax[2], smax[3]));
        ctamax_sh = m;
        atomicMax(&g_absmax_bits[iOutInt], __float_as_uint(m));
    }
    __syncthreads();

    // append amax candidates: v >= cta_max*(1-4e-6) is a superset of the
    // global-threshold set (cta_max <= global_amax).
    const float cthr = ctamax_sh * (1.0f - 4e-6f);
#pragma unroll
    for (int im = 0; im < 4; im++) {
#pragma unroll
        for (int jn = 0; jn < 8; jn++) {
            int row = bm0 + wm * 64 + im * 16 + g;
            int col = bn0 + wn * 64 + jn * 8 + 2 * t;
#pragma unroll
            for (int v = 0; v < 4; v++) {
                if (acc[im][jn][v] >= cthr) {
                    unsigned idx = (unsigned)(row + (v >> 1) * 8) * 4096u
                                 + (unsigned)(col + (v & 1));
                    unsigned pos = atomicAdd(&g_absmax_bits[candSlot], 1u);
                    if (pos < CAND_CAP) g_cand[candBase + pos] = idx;
                }
            }
        }
    }
}

// Layer 3: exact integer warp-dot, out = sc*acc + b3 (order-free, no quant).
__global__ void __launch_bounds__(512)
layer3_kernel(const float* __restrict__ b3, float* __restrict__ out)
{
    extern __shared__ __nv_bfloat16 w3s[];   // [10][4096] bf16 = 80KB
    const int tid = threadIdx.x;
    {
        const uint4* src = (const uint4*)g_w3q;
        uint4* dst = (uint4*)w3s;
        for (int i = tid; i < OUT_DIM * HIDDEN / 8; i += 512) dst[i] = src[i];
    }
    __syncthreads();

    const int lane = tid & 31;
    const int w    = tid >> 5;
    const int m    = blockIdx.x * 16 + w;

    float acc[OUT_DIM];
#pragma unroll
    for (int n = 0; n < OUT_DIM; n++) acc[n] = 0.f;

    const uint32_t* arow = (const uint32_t*)(g_h2q + (size_t)m * HIDDEN);
    const uint32_t* ws   = (const uint32_t*)w3s;
    for (int k2 = lane; k2 < HIDDEN / 2; k2 += 32) {
        uint32_t av = arow[k2];
        float a0 = __uint_as_float(av << 16);
        float a1 = __uint_as_float(av & 0xffff0000u);
#pragma unroll
        for (int n = 0; n < OUT_DIM; n++) {
            uint32_t wv = ws[n * (HIDDEN / 2) + k2];
            acc[n] = fmaf(a0, __uint_as_float(wv << 16), acc[n]);
            acc[n] = fmaf(a1, __uint_as_float(wv & 0xffff0000u), acc[n]);
        }
    }
#pragma unroll
    for (int n = 0; n < OUT_DIM; n++)
#pragma unroll
        for (int o = 16; o; o >>= 1)
            acc[n] += __shfl_xor_sync(0xffffffffu, acc[n], o);

    if (lane == 0) {
        float sc = load_scale(7, 7.f) * load_scale(3, 127.f);
#pragma unroll
        for (int n = 0; n < OUT_DIM; n++)
            out[(size_t)m * OUT_DIM + n] = fmaf(acc[n], sc, b3[n]);
    }
}

extern "C" void kernel_launch(void* const* d_in, const int* in_sizes, int n_in,
                              void* d_out, int out_size) {
    const float* x  = (const float*)d_in[0];
    const float* W1 = (const float*)d_in[1];
    const float* b1 = (const float*)d_in[2];
    const float* W2 = (const float*)d_in[3];
    const float* b2 = (const float*)d_in[4];
    const float* W3 = (const float*)d_in[5];
    const float* b3 = (const float*)d_in[6];
    float* out = (float*)d_out;

    void* p;
    cudaGetSymbolAddress(&p, g_xq);  __nv_bfloat16* xq  = (__nv_bfloat16*)p;
    cudaGetSymbolAddress(&p, g_w1q); __nv_bfloat16* w1q = (__nv_bfloat16*)p;
    cudaGetSymbolAddress(&p, g_w2q); __nv_bfloat16* w2q = (__nv_bfloat16*)p;
    cudaGetSymbolAddress(&p, g_w3q); __nv_bfloat16* w3q = (__nv_bfloat16*)p;
    cudaGetSymbolAddress(&p, g_h1);  float*         h1  = (float*)p;
    cudaGetSymbolAddress(&p, g_h1q); __nv_bfloat16* h1q = (__nv_bfloat16*)p;
    cudaGetSymbolAddress(&p, g_h2);  float*         h2  = (float*)p;
    cudaGetSymbolAddress(&p, g_h2q); __nv_bfloat16* h2q = (__nv_bfloat16*)p;

    const size_t gemm_shm = (size_t)NSTAGE * STAGE_ELEMS * sizeof(__nv_bfloat16); // 96KB
    const size_t l3_shm   = (size_t)OUT_DIM * HIDDEN * sizeof(__nv_bfloat16);     // 80KB
    cudaFuncSetAttribute(gemm_bf16_kernel,
                         cudaFuncAttributeMaxDynamicSharedMemorySize, (int)gemm_shm);
    cudaFuncSetAttribute(layer3_kernel,
                         cudaFuncAttributeMaxDynamicSharedMemorySize, (int)l3_shm);

    init_stats_kernel<<<1, 32>>>();

    // Fused absmax: slot = blockIdx.y (0=x, 1=W1, 2=W2, 3=W3)
    {
        AbsSeg s0 = { x,  BATCH * IN_DIM / 4 };
        AbsSeg s1 = { W1, HIDDEN * IN_DIM / 4 };
        AbsSeg s2 = { W2, HIDDEN * HIDDEN / 4 };
        AbsSeg s3 = { W3, OUT_DIM * HIDDEN / 4 };
        dim3 g(1024, 4);
        absmax4_kernel<<<g, 256>>>(s0, s1, s2, s3);
    }

    // Fused quantize: 4 segments in one launch
    {
        QSeg s0 = { x,  xq,  IN_DIM, K1PAD, 0, BATCH  * (K1PAD / 4), 7.f };
        QSeg s1 = { W1, w1q, IN_DIM, K1PAD, 1, HIDDEN * (K1PAD / 4), 127.f };
        QSeg s2 = { W2, w2q, HIDDEN, HIDDEN, 2, HIDDEN * (HIDDEN / 4), 127.f };
        QSeg s3 = { W3, w3q, HIDDEN, HIDDEN, 3, OUT_DIM * (HIDDEN / 4), 127.f };
        dim3 g(4096, 4);
        quantize4_kernel<<<g, 256>>>(s0, s1, s2, s3);
    }

    dim3 gg(HIDDEN / GBN, BATCH / GBM);  // (32, 128)
    const int NEL = BATCH * HIDDEN;      // 2^26

    // ---- Layer 1 ----
    gemm_bf16_kernel<<<gg, 128, gemm_shm>>>(xq, w1q, b1, h1,
                                            BATCH, HIDDEN, K1PAD,
                                            0, 7.f, 1, 127.f, 4, 10, 0u);
    chain_amax_cand_kernel<<<64, 256>>>(h1, xq, w1q, b1, K1PAD, 4, 6, 10, 0u,
                                        0, 7.f, 1, 127.f);
    quantize_detect_kernel<<<NEL / 1024, 256>>>(h1, h1q, 6, 8, 0u);
    repair_kernel<<<2048, 256>>>(xq, w1q, b1, h1q, K1PAD, 8, 0u,
                                 0, 7.f, 1, 127.f, 6);

    // ---- Layer 2 ----
    gemm_bf16_kernel<<<gg, 128, gemm_shm>>>(h1q, w2q, b2, h2,
                                            BATCH, HIDDEN, HIDDEN,
                                            6, 7.f, 2, 127.f, 5, 11, CAND_CAP);
    chain_amax_cand_kernel<<<64, 256>>>(h2, h1q, w2q, b2, HIDDEN, 5, 7, 11, CAND_CAP,
                                        6, 7.f, 2, 127.f);
    quantize_detect_kernel<<<NEL / 1024, 256>>>(h2, h2q, 7, 9, LIST_CAP);
    repair_kernel<<<2048, 256>>>(h1q, w2q, b2, h2q, HIDDEN, 9, LIST_CAP,
                                 6, 7.f, 2, 127.f, 7);

    // ---- Layer 3 ----
    layer3_kernel<<<BATCH / 16, 512, l3_shm>>>(b3, out);
}

// round 16
// speedup vs baseline: 1.0693x; 1.0597x over previous
#include <cuda_runtime.h>
#include <cuda_bf16.h>
#include <cstdint>
#include <cstddef>

// ---------------------------------------------------------------------------
// QuantizedNN hybrid v11: v10 + register-level fragment double-buffering in
// the GEMM mainloop (ldmatrix for step s+1 issued before MMAs of step s).
// Integer-exact bf16 HMMA GEMM + round-3-exact chain amax / boundary repair.
// h bits identical to rounds 5..15.
// ---------------------------------------------------------------------------

#define BATCH   16384
#define IN_DIM  784
#define K1PAD   832          // 13 * 64 zero-padded K for layer 1
#define HIDDEN  4096
#define OUT_DIM 10

#define GBM 128
#define GBN 128
#define GBK 64
#define NSTAGE 3
#define STAGE_ELEMS ((GBM + GBN) * GBK)   // 16384 bf16 = 32KB per stage

#define LIST_CAP (1u << 22)
#define CAND_CAP (1u << 16)
#define TAU 3e-4f                          // bin-boundary margin (bin units)

// slots: 0=x,1=W1,2=W2,3=W3 | 4,5 = int amax h1,h2 | 6,7 = chain amax h1,h2
//        8,9 = repair counts L1,L2 | 10,11 = amax-candidate counts L1,L2
__device__ unsigned g_absmax_bits[16];
__device__ unsigned g_list[2 * LIST_CAP];
__device__ unsigned g_cand[2 * CAND_CAP];

__device__ __nv_bfloat16 g_xq [(size_t)BATCH  * K1PAD];
__device__ __nv_bfloat16 g_w1q[(size_t)HIDDEN * K1PAD];
__device__ __nv_bfloat16 g_w2q[(size_t)HIDDEN * HIDDEN];
__device__ __nv_bfloat16 g_w3q[(size_t)OUT_DIM * HIDDEN];
__device__ float         g_h1 [(size_t)BATCH * HIDDEN];
__device__ __nv_bfloat16 g_h1q[(size_t)BATCH * HIDDEN];
__device__ float         g_h2 [(size_t)BATCH * HIDDEN];
__device__ __nv_bfloat16 g_h2q[(size_t)BATCH * HIDDEN];

__device__ __forceinline__ float load_scale(int idx, float nlev) {
    float amax = __uint_as_float(g_absmax_bits[idx]);
    return fmaxf(__fdiv_rn(amax, nlev), 1e-8f);   // jnp.maximum(amax/n, 1e-8)
}

__global__ void init_stats_kernel() {
    if (threadIdx.x < 16) g_absmax_bits[threadIdx.x] = 0u;
}

// Fused absmax over 4 tensors: blockIdx.y = tensor id (slot id).
struct AbsSeg { const float* p; int n4; };

__global__ void absmax4_kernel(AbsSeg s0, AbsSeg s1, AbsSeg s2, AbsSeg s3) {
    AbsSeg seg = (blockIdx.y == 0) ? s0 : (blockIdx.y == 1) ? s1
               : (blockIdx.y == 2) ? s2 : s3;
    const float4* x4 = (const float4*)seg.p;
    float m = 0.f;
    for (int i = blockIdx.x * blockDim.x + threadIdx.x; i < seg.n4;
         i += gridDim.x * blockDim.x) {
        float4 v = x4[i];
        m = fmaxf(m, fmaxf(fmaxf(fabsf(v.x), fabsf(v.y)),
                           fmaxf(fabsf(v.z), fabsf(v.w))));
    }
#pragma unroll
    for (int o = 16; o; o >>= 1) m = fmaxf(m, __shfl_xor_sync(0xffffffffu, m, o));
    __shared__ float red[8];
    int lane = threadIdx.x & 31, w = threadIdx.x >> 5;
    if (lane == 0) red[w] = m;
    __syncthreads();
    if (threadIdx.x == 0) {
        float r = red[0];
        for (int i = 1; i < (int)(blockDim.x >> 5); i++) r = fmaxf(r, red[i]);
        atomicMax(&g_absmax_bits[blockIdx.y], __float_as_uint(r));
    }
}

// Fused integer quantize over 4 tensors: blockIdx.y = segment.
struct QSeg {
    const float* in; __nv_bfloat16* out;
    int K, Kpad, statIdx, nchunk;   // nchunk = rows * Kpad/4
    float nlev;
};

__global__ void quantize4_kernel(QSeg s0, QSeg s1, QSeg s2, QSeg s3) {
    QSeg seg = (blockIdx.y == 0) ? s0 : (blockIdx.y == 1) ? s1
             : (blockIdx.y == 2) ? s2 : s3;
    const int kp4 = seg.Kpad >> 2;
    const float s = load_scale(seg.statIdx, seg.nlev);
    const float nlev = seg.nlev;
    for (int idx = blockIdx.x * blockDim.x + threadIdx.x; idx < seg.nchunk;
         idx += gridDim.x * blockDim.x) {
        int r  = idx / kp4;
        int c  = (idx - r * kp4) * 4;
        uint2 packed;
        if (c < seg.K) {
            float4 v = *(const float4*)(seg.in + (size_t)r * seg.K + c);
            float q0 = fminf(fmaxf(rintf(__fdiv_rn(v.x, s)), -nlev), nlev);
            float q1 = fminf(fmaxf(rintf(__fdiv_rn(v.y, s)), -nlev), nlev);
            float q2 = fminf(fmaxf(rintf(__fdiv_rn(v.z, s)), -nlev), nlev);
            float q3 = fminf(fmaxf(rintf(__fdiv_rn(v.w, s)), -nlev), nlev);
            __nv_bfloat162 lo = __floats2bfloat162_rn(q0, q1);
            __nv_bfloat162 hi = __floats2bfloat162_rn(q2, q3);
            packed.x = *(uint32_t*)&lo;
            packed.y = *(uint32_t*)&hi;
        } else {
            packed.x = 0u; packed.y = 0u;
        }
        *(uint2*)(seg.out + (size_t)r * seg.Kpad + c) = packed;
    }
}

// Exact reference-matching value: ascending-k single-accumulator fmaf chain.
__device__ __forceinline__ float chain_value(const __nv_bfloat16* __restrict__ A,
                                             const __nv_bfloat16* __restrict__ W,
                                             const float* __restrict__ bias,
                                             int K, unsigned r, unsigned c,
                                             float sA, float sW) {
    const uint4* a4 = (const uint4*)(A + (size_t)r * K);
    const uint4* w4 = (const uint4*)(W + (size_t)c * K);
    float acc = 0.f;
    for (int kc = 0; kc < K / 8; kc++) {
        uint4 ua = __ldg(&a4[kc]);
        uint4 uw = __ldg(&w4[kc]);
        const __nv_bfloat162* pa = (const __nv_bfloat162*)&ua;
        const __nv_bfloat162* pw = (const __nv_bfloat162*)&uw;
#pragma unroll
        for (int j = 0; j < 4; j++) {
            float2 fa = __bfloat1622float2(pa[j]);
            float2 fw = __bfloat1622float2(pw[j]);
            acc = fmaf(__fmul_rn(fa.x, sA), __fmul_rn(fw.x, sW), acc);
            acc = fmaf(__fmul_rn(fa.y, sA), __fmul_rn(fw.y, sW), acc);
        }
    }
    return fmaxf(__fadd_rn(acc, __ldg(&bias[c])), 0.f);
}

// chain amax over epilogue-collected candidates (superset of global-thr set).
__global__ void chain_amax_cand_kernel(const float* __restrict__ h,
                                       const __nv_bfloat16* __restrict__ Aq,
                                       const __nv_bfloat16* __restrict__ Wq,
                                       const float* __restrict__ bias,
                                       int K, int intSlot, int chainSlot,
                                       int candSlot, unsigned candBase,
                                       int iA, float nA, int iW, float nW) {
    unsigned cnt = g_absmax_bits[candSlot];
    if (cnt > CAND_CAP) cnt = CAND_CAP;
    float amax = __uint_as_float(g_absmax_bits[intSlot]);
    float thr  = amax * (1.0f - 4e-6f);
    const float sA = load_scale(iA, nA);
    const float sW = load_scale(iW, nW);
    for (unsigned i = blockIdx.x * blockDim.x + threadIdx.x; i < cnt;
         i += gridDim.x * blockDim.x) {
        unsigned idx = g_cand[candBase + i];
        if (h[idx] >= thr) {
            unsigned r = idx >> 12, c = idx & 4095u;
            float hv = chain_value(Aq, Wq, bias, K, r, c, sA, sW);
            atomicMax(&g_absmax_bits[chainSlot], __float_as_uint(hv));
        }
    }
}

// quantize h with the CHAIN scale, 4 elems/thread; flag near-boundary.
__global__ void quantize_detect_kernel(const float* __restrict__ h,
                                       __nv_bfloat16* __restrict__ qout,
                                       int chainSlot, int cntSlot,
                                       unsigned listBase) {
    int i4 = blockIdx.x * blockDim.x + threadIdx.x;
    float s = load_scale(chainSlot, 7.f);
    float4 v = __ldcs((const float4*)h + i4);
    float q[4];
    unsigned flags = 0;
    const float* vp = (const float*)&v;
#pragma unroll
    for (int j = 0; j < 4; j++) {
        float t = __fdiv_rn(vp[j], s);
        float r = rintf(t);
        q[j] = fminf(fmaxf(r, -7.f), 7.f);
        if (fabsf(t - r) > 0.5f - TAU) flags |= (1u << j);
    }
    __nv_bfloat162 lo = __floats2bfloat162_rn(q[0], q[1]);
    __nv_bfloat162 hi = __floats2bfloat162_rn(q[2], q[3]);
    uint2 packed; packed.x = *(uint32_t*)&lo; packed.y = *(uint32_t*)&hi;
    *(uint2*)(qout + (size_t)i4 * 4) = packed;
    if (flags) {
#pragma unroll
        for (int j = 0; j < 4; j++) {
            if (flags & (1u << j)) {
                unsigned p = atomicAdd(&g_absmax_bits[cntSlot], 1u);
                if (p < LIST_CAP) g_list[listBase + p] = (unsigned)(i4 * 4 + j);
            }
        }
    }
}

// repair: recompute flagged elements with the exact chain, re-bin, overwrite.
__global__ void repair_kernel(const __nv_bfloat16* __restrict__ Aq,
                              const __nv_bfloat16* __restrict__ Wq,
                              const float* __restrict__ bias,
                              __nv_bfloat16* __restrict__ qout,
                              int K, int cntSlot, unsigned listBase,
                              int iA, float nA, int iW, float nW,
                              int chainSlot) {
    unsigned cnt = g_absmax_bits[cntSlot];
    if (cnt > LIST_CAP) cnt = LIST_CAP;
    const float sA = load_scale(iA, nA);
    const float sW = load_scale(iW, nW);
    const float sO = load_scale(chainSlot, 7.f);
    for (unsigned i = blockIdx.x * blockDim.x + threadIdx.x; i < cnt;
         i += gridDim.x * blockDim.x) {
        unsigned idx = g_list[listBase + i];
        unsigned r = idx >> 12, c = idx & 4095u;
        float hv = chain_value(Aq, Wq, bias, K, r, c, sA, sW);
        float t  = __fdiv_rn(hv, sO);
        float q  = fminf(fmaxf(rintf(t), -7.f), 7.f);
        qout[idx] = __float2bfloat16_rn(q);
    }
}

__device__ __forceinline__ uint32_t smem_u32(const void* p) {
    return (uint32_t)__cvta_generic_to_shared(p);
}

// One stage: A 128 rows x 128B + B 128 rows x 128B, xor-swizzled 16B chunks.
__device__ __forceinline__ void load_stage(__nv_bfloat16* stage,
                                           const __nv_bfloat16* __restrict__ A,
                                           const __nv_bfloat16* __restrict__ B,
                                           int K, int bm0, int bn0, int kt,
                                           int lrow, int lcol)
{
    __nv_bfloat16* as = stage;
    __nv_bfloat16* bs = stage + GBM * GBK;
    const int kbase = kt * GBK + (lcol << 3);
#pragma unroll
    for (int i = 0; i < 8; i++) {
        int r = i * 16 + lrow;
        uint32_t dst = smem_u32(as + r * GBK + ((lcol ^ (r & 7)) << 3));
        asm volatile("cp.async.cg.shared.global [%0], [%1], 16;\n"
                     :: "r"(dst), "l"(A + (size_t)(bm0 + r) * K + kbase));
    }
#pragma unroll
    for (int i = 0; i < 8; i++) {
        int r = i * 16 + lrow;
        uint32_t dst = smem_u32(bs + r * GBK + ((lcol ^ (r & 7)) << 3));
        asm volatile("cp.async.cg.shared.global [%0], [%1], 16;\n"
                     :: "r"(dst), "l"(B + (size_t)(bn0 + r) * K + kbase));
    }
    asm volatile("cp.async.commit_group;\n" ::: "memory");
}

// fragment loads for one k-step s (chunk pair {2s, 2s+1})
__device__ __forceinline__ void load_frags(const __nv_bfloat16* as,
                                           const __nv_bfloat16* bs,
                                           int s, int lane, int wm, int wn,
                                           uint32_t af[4][4], uint32_t bfr[8][2])
{
#pragma unroll
    for (int im = 0; im < 4; im++) {
        int r  = wm * 64 + im * 16 + (lane & 15);
        int ch = (2 * s + (lane >> 4)) ^ (r & 7);
        uint32_t addr = smem_u32(as + r * GBK + ch * 8);
        asm volatile(
            "ldmatrix.sync.aligned.m8n8.x4.shared.b16 {%0,%1,%2,%3}, [%4];"
            : "=r"(af[im][0]), "=r"(af[im][1]), "=r"(af[im][2]), "=r"(af[im][3])
            : "r"(addr));
    }
#pragma unroll
    for (int p = 0; p < 4; p++) {
        int sub = lane >> 3;
        int jn  = 2 * p + (sub >> 1);
        int r   = wn * 64 + jn * 8 + (lane & 7);
        int ch  = (2 * s + (sub & 1)) ^ (r & 7);
        uint32_t addr = smem_u32(bs + r * GBK + ch * 8);
        asm volatile(
            "ldmatrix.sync.aligned.m8n8.x4.shared.b16 {%0,%1,%2,%3}, [%4];"
            : "=r"(bfr[2*p][0]), "=r"(bfr[2*p][1]),
              "=r"(bfr[2*p+1][0]), "=r"(bfr[2*p+1][1])
            : "r"(addr));
    }
}

// C = sc * (Aq @ Bq^T) + bias, relu, int amax -> iOutInt, amax candidates.
// 4 warps x 64x64 sub-tile; register double-buffered fragments.
__global__ void __launch_bounds__(128, 2)
gemm_bf16_kernel(const __nv_bfloat16* __restrict__ A,
                 const __nv_bfloat16* __restrict__ B,
                 const float* __restrict__ bias,
                 float* __restrict__ C,
                 int M, int N, int K,
                 int iA, float nA, int iW, float nW,
                 int iOutInt, int candSlot, unsigned candBase)
{
    extern __shared__ __nv_bfloat16 smem[];
    const int tid  = threadIdx.x;
    const int lane = tid & 31;
    const int wid  = tid >> 5;
    const int wm   = wid >> 1;   // 0..1 : 64 rows
    const int wn   = wid & 1;    // 0..1 : 64 cols
    const int bm0  = blockIdx.y * GBM;
    const int bn0  = blockIdx.x * GBN;
    const int lrow = tid >> 3;   // 0..15
    const int lcol = tid & 7;    // 16B chunk

    float acc[4][8][4];
#pragma unroll
    for (int i = 0; i < 4; i++)
#pragma unroll
        for (int j = 0; j < 8; j++)
#pragma unroll
            for (int v = 0; v < 4; v++) acc[i][j][v] = 0.f;

    uint32_t af2[2][4][4];
    uint32_t bfr2[2][8][2];

    const int nkt = K / GBK;
    load_stage(smem, A, B, K, bm0, bn0, 0, lrow, lcol);
    if (nkt > 1) load_stage(smem + STAGE_ELEMS, A, B, K, bm0, bn0, 1, lrow, lcol);

    for (int kt = 0; kt < nkt; kt++) {
        if (kt + 1 < nkt) {
            asm volatile("cp.async.wait_group 1;\n" ::: "memory");
        } else {
            asm volatile("cp.async.wait_group 0;\n" ::: "memory");
        }
        __syncthreads();   // single barrier per iteration (3-stage buffer)

        const __nv_bfloat16* as = smem + (kt % NSTAGE) * STAGE_ELEMS;
        const __nv_bfloat16* bs = as + GBM * GBK;

        // fragments for s=0 first, then prefetch next stage's gmem
        load_frags(as, bs, 0, lane, wm, wn, af2[0], bfr2[0]);

        if (kt + 2 < nkt) {
            load_stage(smem + ((kt + 2) % NSTAGE) * STAGE_ELEMS, A, B, K,
                       bm0, bn0, kt + 2, lrow, lcol);
        }

#pragma unroll
        for (int s = 0; s < 4; s++) {
            const int cur = s & 1;
            if (s < 3)
                load_frags(as, bs, s + 1, lane, wm, wn, af2[cur ^ 1], bfr2[cur ^ 1]);
#pragma unroll
            for (int im = 0; im < 4; im++)
#pragma unroll
                for (int jn = 0; jn < 8; jn++) {
                    asm volatile(
                        "mma.sync.aligned.m16n8k16.row.col.f32.bf16.bf16.f32 "
                        "{%0,%1,%2,%3}, {%4,%5,%6,%7}, {%8,%9}, {%0,%1,%2,%3};"
                        : "+f"(acc[im][jn][0]), "+f"(acc[im][jn][1]),
                          "+f"(acc[im][jn][2]), "+f"(acc[im][jn][3])
                        : "r"(af2[cur][im][0]), "r"(af2[cur][im][1]),
                          "r"(af2[cur][im][2]), "r"(af2[cur][im][3]),
                          "r"(bfr2[cur][jn][0]), "r"(bfr2[cur][jn][1]));
                }
        }
    }

    const float sc = load_scale(iA, nA) * load_scale(iW, nW);
    const int g = lane >> 2, t = lane & 3;
    float lmax = 0.f;
#pragma unroll
    for (int im = 0; im < 4; im++) {
#pragma unroll
        for (int jn = 0; jn < 8; jn++) {
            int row = bm0 + wm * 64 + im * 16 + g;
            int col = bn0 + wn * 64 + jn * 8 + 2 * t;
            float bv0 = __ldg(&bias[col]), bv1 = __ldg(&bias[col + 1]);
            float v00 = fmaxf(fmaf(acc[im][jn][0], sc, bv0), 0.f);
            float v01 = fmaxf(fmaf(acc[im][jn][1], sc, bv1), 0.f);
            float v10 = fmaxf(fmaf(acc[im][jn][2], sc, bv0), 0.f);
            float v11 = fmaxf(fmaf(acc[im][jn][3], sc, bv1), 0.f);
            acc[im][jn][0] = v00; acc[im][jn][1] = v01;   // keep for candidates
            acc[im][jn][2] = v10; acc[im][jn][3] = v11;
            __stcs((float2*)&C[(size_t)row * N + col],       make_float2(v00, v01));
            __stcs((float2*)&C[(size_t)(row + 8) * N + col], make_float2(v10, v11));
            lmax = fmaxf(lmax, fmaxf(fmaxf(v00, v01), fmaxf(v10, v11)));
        }
    }
#pragma unroll
    for (int o = 16; o; o >>= 1)
        lmax = fmaxf(lmax, __shfl_xor_sync(0xffffffffu, lmax, o));
    __shared__ float smax[4];
    __shared__ float ctamax_sh;
    if (lane == 0) smax[wid] = lmax;
    __syncthreads();
    if (tid == 0) {
        float m = fmaxf(fmaxf(smax[0], smax[1]), fmaxf(smax[2], smax[3]));
        ctamax_sh = m;
        atomicMax(&g_absmax_bits[iOutInt], __float_as_uint(m));
    }
    __syncthreads();

    // append amax candidates: v >= cta_max*(1-4e-6) is a superset of the
    // global-threshold set (cta_max <= global_amax).
    const float cthr = ctamax_sh * (1.0f - 4e-6f);
#pragma unroll
    for (int im = 0; im < 4; im++) {
#pragma unroll
        for (int jn = 0; jn < 8; jn++) {
            int row = bm0 + wm * 64 + im * 16 + g;
            int col = bn0 + wn * 64 + jn * 8 + 2 * t;
#pragma unroll
            for (int v = 0; v < 4; v++) {
                if (acc[im][jn][v] >= cthr) {
                    unsigned idx = (unsigned)(row + (v >> 1) * 8) * 4096u
                                 + (unsigned)(col + (v & 1));
                    unsigned pos = atomicAdd(&g_absmax_bits[candSlot], 1u);
                    if (pos < CAND_CAP) g_cand[candBase + pos] = idx;
                }
            }
        }
    }
}

// Layer 3: exact integer warp-dot, out = sc*acc + b3 (order-free, no quant).
__global__ void __launch_bounds__(512)
layer3_kernel(const float* __restrict__ b3, float* __restrict__ out)
{
    extern __shared__ __nv_bfloat16 w3s[];   // [10][4096] bf16 = 80KB
    const int tid = threadIdx.x;
    {
        const uint4* src = (const uint4*)g_w3q;
        uint4* dst = (uint4*)w3s;
        for (int i = tid; i < OUT_DIM * HIDDEN / 8; i += 512) dst[i] = src[i];
    }
    __syncthreads();

    const int lane = tid & 31;
    const int w    = tid >> 5;
    const int m    = blockIdx.x * 16 + w;

    float acc[OUT_DIM];
#pragma unroll
    for (int n = 0; n < OUT_DIM; n++) acc[n] = 0.f;

    const uint32_t* arow = (const uint32_t*)(g_h2q + (size_t)m * HIDDEN);
    const uint32_t* ws   = (const uint32_t*)w3s;
    for (int k2 = lane; k2 < HIDDEN / 2; k2 += 32) {
        uint32_t av = arow[k2];
        float a0 = __uint_as_float(av << 16);
        float a1 = __uint_as_float(av & 0xffff0000u);
#pragma unroll
        for (int n = 0; n < OUT_DIM; n++) {
            uint32_t wv = ws[n * (HIDDEN / 2) + k2];
            acc[n] = fmaf(a0, __uint_as_float(wv << 16), acc[n]);
            acc[n] = fmaf(a1, __uint_as_float(wv & 0xffff0000u), acc[n]);
        }
    }
#pragma unroll
    for (int n = 0; n < OUT_DIM; n++)
#pragma unroll
        for (int o = 16; o; o >>= 1)
            acc[n] += __shfl_xor_sync(0xffffffffu, acc[n], o);

    if (lane == 0) {
        float sc = load_scale(7, 7.f) * load_scale(3, 127.f);
#pragma unroll
        for (int n = 0; n < OUT_DIM; n++)
            out[(size_t)m * OUT_DIM + n] = fmaf(acc[n], sc, b3[n]);
    }
}

extern "C" void kernel_launch(void* const* d_in, const int* in_sizes, int n_in,
                              void* d_out, int out_size) {
    const float* x  = (const float*)d_in[0];
    const float* W1 = (const float*)d_in[1];
    const float* b1 = (const float*)d_in[2];
    const float* W2 = (const float*)d_in[3];
    const float* b2 = (const float*)d_in[4];
    const float* W3 = (const float*)d_in[5];
    const float* b3 = (const float*)d_in[6];
    float* out = (float*)d_out;

    void* p;
    cudaGetSymbolAddress(&p, g_xq);  __nv_bfloat16* xq  = (__nv_bfloat16*)p;
    cudaGetSymbolAddress(&p, g_w1q); __nv_bfloat16* w1q = (__nv_bfloat16*)p;
    cudaGetSymbolAddress(&p, g_w2q); __nv_bfloat16* w2q = (__nv_bfloat16*)p;
    cudaGetSymbolAddress(&p, g_w3q); __nv_bfloat16* w3q = (__nv_bfloat16*)p;
    cudaGetSymbolAddress(&p, g_h1);  float*         h1  = (float*)p;
    cudaGetSymbolAddress(&p, g_h1q); __nv_bfloat16* h1q = (__nv_bfloat16*)p;
    cudaGetSymbolAddress(&p, g_h2);  float*         h2  = (float*)p;
    cudaGetSymbolAddress(&p, g_h2q); __nv_bfloat16* h2q = (__nv_bfloat16*)p;

    const size_t gemm_shm = (size_t)NSTAGE * STAGE_ELEMS * sizeof(__nv_bfloat16); // 96KB
    const size_t l3_shm   = (size_t)OUT_DIM * HIDDEN * sizeof(__nv_bfloat16);     // 80KB
    cudaFuncSetAttribute(gemm_bf16_kernel,
                         cudaFuncAttributeMaxDynamicSharedMemorySize, (int)gemm_shm);
    cudaFuncSetAttribute(layer3_kernel,
                         cudaFuncAttributeMaxDynamicSharedMemorySize, (int)l3_shm);

    init_stats_kernel<<<1, 32>>>();

    // Fused absmax: slot = blockIdx.y (0=x, 1=W1, 2=W2, 3=W3)
    {
        AbsSeg s0 = { x,  BATCH * IN_DIM / 4 };
        AbsSeg s1 = { W1, HIDDEN * IN_DIM / 4 };
        AbsSeg s2 = { W2, HIDDEN * HIDDEN / 4 };
        AbsSeg s3 = { W3, OUT_DIM * HIDDEN / 4 };
        dim3 g(1024, 4);
        absmax4_kernel<<<g, 256>>>(s0, s1, s2, s3);
    }

    // Fused quantize: 4 segments in one launch
    {
        QSeg s0 = { x,  xq,  IN_DIM, K1PAD, 0, BATCH  * (K1PAD / 4), 7.f };
        QSeg s1 = { W1, w1q, IN_DIM, K1PAD, 1, HIDDEN * (K1PAD / 4), 127.f };
        QSeg s2 = { W2, w2q, HIDDEN, HIDDEN, 2, HIDDEN * (HIDDEN / 4), 127.f };
        QSeg s3 = { W3, w3q, HIDDEN, HIDDEN, 3, OUT_DIM * (HIDDEN / 4), 127.f };
        dim3 g(4096, 4);
        quantize4_kernel<<<g, 256>>>(s0, s1, s2, s3);
    }

    dim3 gg(HIDDEN / GBN, BATCH / GBM);  // (32, 128)
    const int NEL = BATCH * HIDDEN;      // 2^26

    // ---- Layer 1 ----
    gemm_bf16_kernel<<<gg, 128, gemm_shm>>>(xq, w1q, b1, h1,
                                            BATCH, HIDDEN, K1PAD,
                                            0, 7.f, 1, 127.f, 4, 10, 0u);
    chain_amax_cand_kernel<<<64, 256>>>(h1, xq, w1q, b1, K1PAD, 4, 6, 10, 0u,
                                        0, 7.f, 1, 127.f);
    quantize_detect_kernel<<<NEL / 1024, 256>>>(h1, h1q, 6, 8, 0u);
    repair_kernel<<<2048, 256>>>(xq, w1q, b1, h1q, K1PAD, 8, 0u,
                                 0, 7.f, 1, 127.f, 6);

    // ---- Layer 2 ----
    gemm_bf16_kernel<<<gg, 128, gemm_shm>>>(h1q, w2q, b2, h2,
                                            BATCH, HIDDEN, HIDDEN,
                                            6, 7.f, 2, 127.f, 5, 11, CAND_CAP);
    chain_amax_cand_kernel<<<64, 256>>>(h2, h1q, w2q, b2, HIDDEN, 5, 7, 11, CAND_CAP,
                                        6, 7.f, 2, 127.f);
    quantize_detect_kernel<<<NEL / 1024, 256>>>(h2, h2q, 7, 9, LIST_CAP);
    repair_kernel<<<2048, 256>>>(h1q, w2q, b2, h2q, HIDDEN, 9, LIST_CAP,
                                 6, 7.f, 2, 127.f, 7);

    // ---- Layer 3 ----
    layer3_kernel<<<BATCH / 16, 512, l3_shm>>>(b3, out);
}